// round 3
// baseline (speedup 1.0000x reference)
#include <cuda_runtime.h>
#include <stdint.h>
#include <math.h>

#define B_   4
#define N_   4096
#define DIM_ 512
#define H_   8
#define DH_  64
#define M_   256
#define BH_  32

// ---------------- scratch ----------------------------------------------------
__device__ float g_q  [BH_*N_*DH_];
__device__ float g_k  [BH_*N_*DH_];
__device__ float g_v  [BH_*N_*DH_];
__device__ float g_qlm[BH_*M_*DH_];
__device__ float g_klm[BH_*M_*DH_];
__device__ float g_s1 [BH_*N_*M_];
__device__ float g_a2 [BH_*M_*M_];
__device__ float g_s3 [BH_*M_*N_];
__device__ float g_z  [BH_*M_*M_];
__device__ float g_z2 [BH_*M_*M_];
__device__ float g_xz [BH_*M_*M_];
__device__ float g_t1 [BH_*M_*M_];
__device__ float g_t3 [BH_*M_*M_];
__device__ float g_t5 [BH_*M_*M_];
__device__ float g_a3v[BH_*M_*DH_];
__device__ float g_zv [BH_*M_*DH_];
__device__ float g_of [B_*N_*DIM_];
__device__ float g_gmax[2];

// ---------------- tf32 helpers -----------------------------------------------
__device__ __forceinline__ uint32_t f2tf(float f) {
    uint32_t u; asm("cvt.rna.tf32.f32 %0, %1;" : "=r"(u) : "f"(f)); return u;
}

__device__ __forceinline__ void mma_tf32(float c[4],
    uint32_t a0, uint32_t a1, uint32_t a2, uint32_t a3, uint32_t b0, uint32_t b1)
{
    asm("mma.sync.aligned.m16n8k8.row.col.f32.tf32.tf32.f32 "
        "{%0,%1,%2,%3}, {%4,%5,%6,%7}, {%8,%9}, {%0,%1,%2,%3};"
        : "+f"(c[0]), "+f"(c[1]), "+f"(c[2]), "+f"(c[3])
        : "r"(a0), "r"(a1), "r"(a2), "r"(a3), "r"(b0), "r"(b1));
}

// ---------------- tensor-core batched GEMM (double-buffered smem) -------------
// C[bz] = epi( A[bz](MxK,row) @ op(B[bz]) )  — 256 threads, tile BM x BN x 16.
// MODE: 0: alpha*acc   2: dval*I - acc   3: C=acc, C2=dval*I-acc
//       4: acc + bias[col]   5: qkv scatter (q scaled 0.125)
//       6: write [b,n,h,d] 'of' layout   7: fused row softmax (BM=64,BN=256)
template<int BM, int BN, int WGM, int WGN, int TRANSB, int MODE>
__global__ void __launch_bounds__(256, 2)
gemm_tc(int K,
        const float* __restrict__ A,  int lda, long long sA,
        const float* __restrict__ Bg, int ldb, long long sB,
        float* __restrict__ C, int ldc, long long sC,
        float alpha, float dval,
        float* __restrict__ C2, const float* __restrict__ bias,
        float* __restrict__ oq, float* __restrict__ okk, float* __restrict__ ov)
{
    constexpr int BK = 16;
    constexpr int WM = BM / WGM, WN = BN / WGN;
    constexpr int MI = WM / 16,  NI = WN / 8;
    constexpr int AI  = (BM * BK) / (256 * 4);
    constexpr int NQ  = BN / 4;
    constexpr int B0I = (BK * BN) / (256 * 4);
    constexpr int B0S = 256 / NQ;
    constexpr int B1I = BN / 64;
    constexpr int BI  = TRANSB ? B1I : B0I;

    __shared__ __align__(16) union SM {
        struct { uint32_t A[2][BK * BM]; uint32_t B[2][BK * BN]; } t;
        float stage[MODE == 7 ? BM * BN : 1];
    } sm;

    const int bz = blockIdx.z;
    A  += (long long)bz * sA;
    Bg += (long long)bz * sB;
    if (MODE != 5 && MODE != 6) C += (long long)bz * sC;
    if (MODE == 3) C2 += (long long)bz * sC;

    const int tid = threadIdx.x;
    const int rowBase = blockIdx.y * BM;
    const int colBase = blockIdx.x * BN;
    const int w = tid >> 5, lane = tid & 31;
    const int wm = w / WGN, wn = w % WGN;
    const int tm = lane >> 2, lq = lane & 3;

    float acc[MI][NI][4];
#pragma unroll
    for (int mi = 0; mi < MI; mi++)
#pragma unroll
        for (int ni = 0; ni < NI; ni++)
#pragma unroll
            for (int r = 0; r < 4; r++) acc[mi][ni][r] = 0.f;

    const int a_k4 = (tid & 3) * 4;
    const int a_m  = tid >> 2;
    const int b0_n = (tid % NQ) * 4;
    const int b0_k = tid / NQ;
    const int b1_k4 = (tid & 3) * 4;
    const int b1_n  = tid >> 2;

    float4 aReg[AI];
    float4 bReg[BI];

    // -------- load helpers (as lambdas via macros through code dup) --------
    auto LDG = [&](int kt) {
#pragma unroll
        for (int i = 0; i < AI; i++)
            aReg[i] = *(const float4*)(A + (long long)(rowBase + a_m + 64 * i) * lda + kt + a_k4);
        if (TRANSB == 0) {
#pragma unroll
            for (int i = 0; i < BI; i++)
                bReg[i] = *(const float4*)(Bg + (long long)(kt + b0_k + B0S * i) * ldb + colBase + b0_n);
        } else {
#pragma unroll
            for (int i = 0; i < BI; i++)
                bReg[i] = *(const float4*)(Bg + (long long)(colBase + b1_n + 64 * i) * ldb + kt + b1_k4);
        }
    };
    auto STS = [&](int buf) {
        uint32_t* As = sm.t.A[buf];
        uint32_t* Bs = sm.t.B[buf];
#pragma unroll
        for (int i = 0; i < AI; i++) {
            int m = a_m + 64 * i;
            As[(a_k4 + 0) * BM + (m ^ 0 )] = f2tf(aReg[i].x);
            As[(a_k4 + 1) * BM + (m ^ 8 )] = f2tf(aReg[i].y);
            As[(a_k4 + 2) * BM + (m ^ 16)] = f2tf(aReg[i].z);
            As[(a_k4 + 3) * BM + (m ^ 24)] = f2tf(aReg[i].w);
        }
        if (TRANSB == 0) {
#pragma unroll
            for (int i = 0; i < BI; i++) {
                int k = b0_k + B0S * i;
                uint4 u;
                u.x = f2tf(bReg[i].x); u.y = f2tf(bReg[i].y);
                u.z = f2tf(bReg[i].z); u.w = f2tf(bReg[i].w);
                *(uint4*)&Bs[k * BN + (b0_n ^ ((k & 3) << 3))] = u;
            }
        } else {
#pragma unroll
            for (int i = 0; i < BI; i++) {
                int n = b1_n + 64 * i;
                Bs[(b1_k4 + 0) * BN + (n ^ 0 )] = f2tf(bReg[i].x);
                Bs[(b1_k4 + 1) * BN + (n ^ 8 )] = f2tf(bReg[i].y);
                Bs[(b1_k4 + 2) * BN + (n ^ 16)] = f2tf(bReg[i].z);
                Bs[(b1_k4 + 3) * BN + (n ^ 24)] = f2tf(bReg[i].w);
            }
        }
    };

    // -------- prologue --------
    LDG(0);
    STS(0);
    __syncthreads();

    // -------- mainloop: one sync per k-tile, STS overlapped with compute ----
    for (int kt = 0; kt < K; kt += BK) {
        const int cur = (kt / BK) & 1;
        const bool more = (kt + BK) < K;
        if (more) LDG(kt + BK);

        const uint32_t* As = sm.t.A[cur];
        const uint32_t* Bs = sm.t.B[cur];
#pragma unroll
        for (int kk = 0; kk < BK; kk += 8) {
            uint32_t af[MI][4], bf[NI][2];
            const int x = lq << 3;
#pragma unroll
            for (int mi = 0; mi < MI; mi++) {
                int m = wm * WM + mi * 16 + tm;
                af[mi][0] = As[(kk + lq)     * BM + ( m      ^ x)];
                af[mi][1] = As[(kk + lq)     * BM + ((m + 8) ^ x)];
                af[mi][2] = As[(kk + lq + 4) * BM + ( m      ^ x)];
                af[mi][3] = As[(kk + lq + 4) * BM + ((m + 8) ^ x)];
            }
#pragma unroll
            for (int ni = 0; ni < NI; ni++) {
                int n = wn * WN + ni * 8 + tm;
                bf[ni][0] = Bs[(kk + lq)     * BN + (n ^ x)];
                bf[ni][1] = Bs[(kk + lq + 4) * BN + (n ^ x)];
            }
#pragma unroll
            for (int mi = 0; mi < MI; mi++)
#pragma unroll
                for (int ni = 0; ni < NI; ni++)
                    mma_tf32(acc[mi][ni], af[mi][0], af[mi][1], af[mi][2], af[mi][3],
                             bf[ni][0], bf[ni][1]);
        }

        if (more) STS(cur ^ 1);
        __syncthreads();
    }

    // -------- epilogue --------
    if (MODE == 7) {
        // stage fp32 tile, block row-softmax, write normalized
#pragma unroll
        for (int mi = 0; mi < MI; mi++) {
            int rl = wm * WM + mi * 16 + tm;
#pragma unroll
            for (int ni = 0; ni < NI; ni++) {
                int cl = wn * WN + ni * 8 + 2 * lq;
#pragma unroll
                for (int half = 0; half < 2; half++) {
                    *(float2*)&sm.stage[(rl + 8 * half) * BN + cl] =
                        make_float2(acc[mi][ni][2 * half], acc[mi][ni][2 * half + 1]);
                }
            }
        }
        __syncthreads();
        // 4 threads per row, 64 cols each
        int row = tid >> 2, seg = tid & 3;
        float* rp = &sm.stage[row * BN + seg * 64];
        float mx = -3.4e38f;
#pragma unroll
        for (int j = 0; j < 64; j += 4) {
            float4 v = *(float4*)&rp[j];
            mx = fmaxf(mx, fmaxf(fmaxf(v.x, v.y), fmaxf(v.z, v.w)));
        }
        mx = fmaxf(mx, __shfl_xor_sync(~0u, mx, 1));
        mx = fmaxf(mx, __shfl_xor_sync(~0u, mx, 2));
        float sum = 0.f;
#pragma unroll
        for (int j = 0; j < 64; j += 4) {
            float4 v = *(float4*)&rp[j];
            v.x = __expf(v.x - mx); v.y = __expf(v.y - mx);
            v.z = __expf(v.z - mx); v.w = __expf(v.w - mx);
            sum += v.x + v.y + v.z + v.w;
            *(float4*)&rp[j] = v;
        }
        sum += __shfl_xor_sync(~0u, sum, 1);
        sum += __shfl_xor_sync(~0u, sum, 2);
        float inv = 1.f / sum;
        float* cp = &C[(long long)(rowBase + row) * ldc + seg * 64];
#pragma unroll
        for (int j = 0; j < 64; j += 4) {
            float4 v = *(float4*)&rp[j];
            v.x *= inv; v.y *= inv; v.z *= inv; v.w *= inv;
            *(float4*)&cp[j] = v;
        }
        return;
    }

#pragma unroll
    for (int mi = 0; mi < MI; mi++) {
        int rBase = rowBase + wm * WM + mi * 16 + tm;
#pragma unroll
        for (int ni = 0; ni < NI; ni++) {
            int c = colBase + wn * WN + ni * 8 + 2 * lq;
#pragma unroll
            for (int half = 0; half < 2; half++) {
                int r = rBase + 8 * half;
                float2 v = make_float2(acc[mi][ni][2 * half], acc[mi][ni][2 * half + 1]);
                if (MODE == 0) {
                    v.x *= alpha; v.y *= alpha;
                    *(float2*)&C[(long long)r * ldc + c] = v;
                } else if (MODE == 2) {
                    v.x = (r == c     ? dval : 0.f) - v.x;
                    v.y = (r == c + 1 ? dval : 0.f) - v.y;
                    *(float2*)&C[(long long)r * ldc + c] = v;
                } else if (MODE == 3) {
                    *(float2*)&C[(long long)r * ldc + c] = v;
                    float2 v2;
                    v2.x = (r == c     ? dval : 0.f) - v.x;
                    v2.y = (r == c + 1 ? dval : 0.f) - v.y;
                    *(float2*)&C2[(long long)r * ldc + c] = v2;
                } else if (MODE == 4) {
                    v.x += bias[c]; v.y += bias[c + 1];
                    *(float2*)&C[(long long)r * ldc + c] = v;
                } else if (MODE == 5) {
                    int b = r >> 12, n = r & 4095;
                    int part = c >> 9, h = (c >> 6) & 7, d = c & 63;
                    if (part == 0) { v.x *= 0.125f; v.y *= 0.125f; }
                    float* dst = (part == 0) ? oq : ((part == 1) ? okk : ov);
                    *(float2*)&dst[((((long long)(b * 8 + h)) << 12) + n) * 64 + d] = v;
                } else { // 6
                    int b = bz >> 3, h = bz & 7;
                    *(float2*)&C[((long long)(b * 4096 + r)) * 512 + h * 64 + c] = v;
                }
            }
        }
    }
}

// ---------------- landmarks ---------------------------------------------------
__global__ void landmarks_kernel(const float* __restrict__ q, const float* __restrict__ k,
                                 float* __restrict__ qlm, float* __restrict__ klm)
{
    int idx = blockIdx.x;          // bh*256 + m
    int d = threadIdx.x;
    long long base = ((long long)idx * 16) * 64 + d;
    float sq = 0.f, sk = 0.f;
#pragma unroll
    for (int j = 0; j < 16; j++) {
        sq += q[base + j * 64];
        sk += k[base + j * 64];
    }
    qlm[(long long)idx * 64 + d] = sq * 0.0625f;
    klm[(long long)idx * 64 + d] = sk * 0.0625f;
}

// ---------------- softmax for 4096-wide rows ------------------------------------
__global__ void softmax4096(float* __restrict__ data)
{
    __shared__ float redm[8], reds[8];
    float4* p = (float4*)(data + ((long long)blockIdx.x << 12));
    int tid = threadIdx.x;
    float4 v[4];
#pragma unroll
    for (int i = 0; i < 4; i++) v[i] = p[tid + 256 * i];
    float m = -3.4e38f;
#pragma unroll
    for (int i = 0; i < 4; i++)
        m = fmaxf(m, fmaxf(fmaxf(v[i].x, v[i].y), fmaxf(v[i].z, v[i].w)));
#pragma unroll
    for (int s = 16; s; s >>= 1) m = fmaxf(m, __shfl_xor_sync(~0u, m, s));
    if ((tid & 31) == 0) redm[tid >> 5] = m;
    __syncthreads();
#pragma unroll
    for (int j = 0; j < 8; j++) m = fmaxf(m, redm[j]);

    float sum = 0.f;
#pragma unroll
    for (int i = 0; i < 4; i++) {
        v[i].x = __expf(v[i].x - m); v[i].y = __expf(v[i].y - m);
        v[i].z = __expf(v[i].z - m); v[i].w = __expf(v[i].w - m);
        sum += v[i].x + v[i].y + v[i].z + v[i].w;
    }
#pragma unroll
    for (int s = 16; s; s >>= 1) sum += __shfl_xor_sync(~0u, sum, s);
    if ((tid & 31) == 0) reds[tid >> 5] = sum;
    __syncthreads();
    sum = 0.f;
#pragma unroll
    for (int j = 0; j < 8; j++) sum += reds[j];
    float inv = 1.f / sum;
#pragma unroll
    for (int i = 0; i < 4; i++) {
        v[i].x *= inv; v[i].y *= inv; v[i].z *= inv; v[i].w *= inv;
        p[tid + 256 * i] = v[i];
    }
}

// ---------------- pinv init ----------------------------------------------------
__global__ void zero_gmax(float* gm) { gm[0] = 0.f; gm[1] = 0.f; }

__global__ void pinv_scales(const float* __restrict__ a, float* gm)
{
    __shared__ float red[256];
    int bh = blockIdx.x, tid = threadIdx.x;
    const float* A = a + ((long long)bh << 16);
    float rs = 0.f;
    for (int j = 0; j < 256; j++) rs += fabsf(A[tid * 256 + j]);
    red[tid] = rs; __syncthreads();
    for (int s = 128; s > 0; s >>= 1) {
        if (tid < s) red[tid] = fmaxf(red[tid], red[tid + s]);
        __syncthreads();
    }
    if (tid == 0) atomicMax((int*)&gm[0], __float_as_int(red[0]));
    __syncthreads();
    float cs = 0.f;
    for (int i = 0; i < 256; i++) cs += fabsf(A[i * 256 + tid]);
    red[tid] = cs; __syncthreads();
    for (int s = 128; s > 0; s >>= 1) {
        if (tid < s) red[tid] = fmaxf(red[tid], red[tid + s]);
        __syncthreads();
    }
    if (tid == 0) atomicMax((int*)&gm[1], __float_as_int(red[0]));
}

__global__ void pinv_init(const float* __restrict__ a, float* __restrict__ z,
                          const float* __restrict__ gm)
{
    long long t = (long long)blockIdx.x * 256 + threadIdx.x;
    int bh = (int)(t >> 16);
    int ij = (int)(t & 65535);
    int i = ij >> 8, j = ij & 255;
    float inv = 1.f / (gm[0] * gm[1]);
    z[((long long)bh << 16) + ij] = a[((long long)bh << 16) + (j << 8) + i] * inv;
}

// ---------------- depthwise conv, accumulates into 'of' layout ------------------
__global__ void conv_add_of(const float* __restrict__ v, const float* __restrict__ w,
                            float* __restrict__ of)
{
    long long t = (long long)blockIdx.x * 256 + threadIdx.x;   // BH*N*DH
    int d = (int)(t & 63);
    long long r = t >> 6;
    int n  = (int)(r & 4095);
    int bh = (int)(r >> 12);
    int h  = bh & 7, b = bh >> 3;
    const float* vp = v + ((long long)bh << 18) + d;
    float s = 0.f;
#pragma unroll
    for (int tp = 0; tp < 33; tp++) {
        int nn = n + tp - 16;
        if (nn >= 0 && nn < 4096)
            s = fmaf(vp[(long long)nn << 6], w[h * 33 + tp], s);
    }
    of[((long long)(b * 4096 + n)) * 512 + h * 64 + d] += s;
}

// ---------------- host orchestration -------------------------------------------
extern "C" void kernel_launch(void* const* d_in, const int* in_sizes, int n_in,
                              void* d_out, int out_size)
{
    const float* x    = (const float*)d_in[0];
    const float* Wqkv = (const float*)d_in[1];
    const float* Wout = (const float*)d_in[2];
    const float* bout = (const float*)d_in[3];
    const float* rk   = (const float*)d_in[4];
    float* yout = (float*)d_out;

    float *q, *k, *v, *qlm, *klm, *s1, *a2, *s3, *z, *z2, *xz, *t1, *t3, *t5,
          *a3v, *zv, *of, *gm;
    cudaGetSymbolAddress((void**)&q,   g_q);
    cudaGetSymbolAddress((void**)&k,   g_k);
    cudaGetSymbolAddress((void**)&v,   g_v);
    cudaGetSymbolAddress((void**)&qlm, g_qlm);
    cudaGetSymbolAddress((void**)&klm, g_klm);
    cudaGetSymbolAddress((void**)&s1,  g_s1);
    cudaGetSymbolAddress((void**)&a2,  g_a2);
    cudaGetSymbolAddress((void**)&s3,  g_s3);
    cudaGetSymbolAddress((void**)&z,   g_z);
    cudaGetSymbolAddress((void**)&z2,  g_z2);
    cudaGetSymbolAddress((void**)&xz,  g_xz);
    cudaGetSymbolAddress((void**)&t1,  g_t1);
    cudaGetSymbolAddress((void**)&t3,  g_t3);
    cudaGetSymbolAddress((void**)&t5,  g_t5);
    cudaGetSymbolAddress((void**)&a3v, g_a3v);
    cudaGetSymbolAddress((void**)&zv,  g_zv);
    cudaGetSymbolAddress((void**)&of,  g_of);
    cudaGetSymbolAddress((void**)&gm,  g_gmax);

    const long long sQ  = (long long)N_ * DH_;   // 262144
    const long long sLM = (long long)M_ * DH_;   // 16384
    const long long sS1 = (long long)N_ * M_;    // 1048576
    const long long sMM = (long long)M_ * M_;    // 65536

    // 1. qkv projection with scatter (q scaled)
    gemm_tc<128,128,2,4,0,5><<<dim3(12, 128, 1), 256>>>(
        512, x, 512, 0, Wqkv, 1536, 0,
        nullptr, 0, 0, 1.f, 0.f, nullptr, nullptr, q, k, v);

    // 2. landmarks
    landmarks_kernel<<<BH_ * M_, DH_>>>(q, k, qlm, klm);

    // 3. attn1 = softmax(q @ klm^T) — fused epilogue softmax (full 256-wide rows)
    gemm_tc<64,256,1,8,1,7><<<dim3(1, 64, BH_), 256>>>(
        64, q, 64, sQ, klm, 64, sLM,
        s1, 256, sS1, 1.f, 0.f, nullptr, nullptr, nullptr, nullptr, nullptr);

    // 4. attn2 = softmax(qlm @ klm^T) — fused
    gemm_tc<64,256,1,8,1,7><<<dim3(1, 4, BH_), 256>>>(
        64, qlm, 64, sLM, klm, 64, sLM,
        a2, 256, sMM, 1.f, 0.f, nullptr, nullptr, nullptr, nullptr, nullptr);

    // 5. sim3 = qlm @ k^T ; softmax (rows of 4096)
    gemm_tc<128,128,2,4,1,0><<<dim3(32, 2, BH_), 256>>>(
        64, qlm, 64, sLM, k, 64, sQ,
        s3, 4096, (long long)M_ * N_, 1.f, 0.f, nullptr, nullptr, nullptr, nullptr, nullptr);
    softmax4096<<<BH_ * M_, 256>>>(s3);

    // 6. pinv init
    zero_gmax<<<1, 1>>>(gm);
    pinv_scales<<<BH_, 256>>>(a2, gm);
    pinv_init<<<(BH_ * M_ * M_) / 256, 256>>>(a2, z, gm);

    // 7. Newton-Schulz x6
    float* za = z;
    float* zb = z2;
    for (int it = 0; it < 6; it++) {
        gemm_tc<128,128,2,4,0,3><<<dim3(2, 2, BH_), 256>>>(
            256, a2, 256, sMM, za, 256, sMM,
            xz, 256, sMM, 1.f, 7.f, t1, nullptr, nullptr, nullptr, nullptr);
        gemm_tc<128,128,2,4,0,2><<<dim3(2, 2, BH_), 256>>>(
            256, xz, 256, sMM, t1, 256, sMM,
            t3, 256, sMM, 1.f, 15.f, nullptr, nullptr, nullptr, nullptr, nullptr);
        gemm_tc<128,128,2,4,0,2><<<dim3(2, 2, BH_), 256>>>(
            256, xz, 256, sMM, t3, 256, sMM,
            t5, 256, sMM, 1.f, 13.f, nullptr, nullptr, nullptr, nullptr, nullptr);
        gemm_tc<128,128,2,4,0,0><<<dim3(2, 2, BH_), 256>>>(
            256, za, 256, sMM, t5, 256, sMM,
            zb, 256, sMM, 0.25f, 0.f, nullptr, nullptr, nullptr, nullptr, nullptr);
        float* sw = za; za = zb; zb = sw;
    }

    // 8. a3v = attn3 @ v   [256 x 64], K=4096
    gemm_tc<128,64,4,2,0,0><<<dim3(1, 2, BH_), 256>>>(
        4096, s3, 4096, (long long)M_ * N_, v, 64, sQ,
        a3v, 64, sLM, 1.f, 0.f, nullptr, nullptr, nullptr, nullptr, nullptr);

    // 9. zv = z @ a3v   [256 x 64], K=256
    gemm_tc<128,64,4,2,0,0><<<dim3(1, 2, BH_), 256>>>(
        256, za, 256, sMM, a3v, 64, sLM,
        zv, 64, sLM, 1.f, 0.f, nullptr, nullptr, nullptr, nullptr, nullptr);

    // 10. out = attn1 @ zv  -> writes 'of' [b,n,h,d] directly
    gemm_tc<128,64,4,2,0,6><<<dim3(1, 32, BH_), 256>>>(
        256, s1, 256, sS1, zv, 64, sLM,
        of, 0, 0, 1.f, 0.f, nullptr, nullptr, nullptr, nullptr, nullptr);

    // 11. += depthwise conv of v (into 'of' layout)
    conv_add_of<<<(BH_ * N_ * DH_) / 256, 256>>>(v, rk, of);

    // 12. final projection: y = of @ Wout + bout
    gemm_tc<128,128,2,4,0,4><<<dim3(4, 128, 1), 256>>>(
        512, of, 512, 0, Wout, 512, 0,
        yout, 512, 0, 1.f, 0.f, nullptr, bout, nullptr, nullptr, nullptr);
}

// round 4
// speedup vs baseline: 1.0667x; 1.0667x over previous
#include <cuda_runtime.h>
#include <stdint.h>
#include <math.h>

#define B_   4
#define N_   4096
#define DIM_ 512
#define H_   8
#define DH_  64
#define M_   256
#define BH_  32

// ---------------- scratch ----------------------------------------------------
__device__ float g_q  [BH_*N_*DH_];
__device__ float g_k  [BH_*N_*DH_];
__device__ float g_v  [BH_*N_*DH_];
__device__ float g_qlm[BH_*M_*DH_];
__device__ float g_klm[BH_*M_*DH_];
__device__ float g_s1 [BH_*N_*M_];
__device__ float g_a2 [BH_*M_*M_];
__device__ float g_s3 [BH_*M_*N_];
__device__ float g_z  [BH_*M_*M_];
__device__ float g_z2 [BH_*M_*M_];
__device__ float g_xz [BH_*M_*M_];
__device__ float g_t1 [BH_*M_*M_];
__device__ float g_t3 [BH_*M_*M_];
__device__ float g_t5 [BH_*M_*M_];
__device__ float g_a3v[BH_*M_*DH_];
__device__ float g_zv [BH_*M_*DH_];
__device__ float g_of [B_*N_*DIM_];
__device__ float g_gmax[2];

// ---------------- tf32 helpers -----------------------------------------------
__device__ __forceinline__ uint32_t f2tf(float f) {
    uint32_t u; asm("cvt.rna.tf32.f32 %0, %1;" : "=r"(u) : "f"(f)); return u;
}

__device__ __forceinline__ void mma_tf32(float c[4],
    uint32_t a0, uint32_t a1, uint32_t a2, uint32_t a3, uint32_t b0, uint32_t b1)
{
    asm("mma.sync.aligned.m16n8k8.row.col.f32.tf32.tf32.f32 "
        "{%0,%1,%2,%3}, {%4,%5,%6,%7}, {%8,%9}, {%0,%1,%2,%3};"
        : "+f"(c[0]), "+f"(c[1]), "+f"(c[2]), "+f"(c[3])
        : "r"(a0), "r"(a1), "r"(a2), "r"(a3), "r"(b0), "r"(b1));
}

// ---------------- tensor-core batched GEMM (double-buffered smem) -------------
// C[bz] = epi( A[bz](MxK,row) @ op(B[bz]) )  — 256 threads, tile BM x BN x 16.
// MODE: 0: alpha*acc   2: dval*I - acc   3: C=acc, C2=dval*I-acc
//       4: acc + bias[col]   5: qkv scatter (q scaled 0.125)
//       6: write [b,n,h,d] 'of' layout
//       7: fused row softmax, register path (requires WGM=1, full row in CTA)
template<int BM, int BN, int WGM, int WGN, int TRANSB, int MODE>
__global__ void __launch_bounds__(256, 2)
gemm_tc(int K,
        const float* __restrict__ A,  int lda, long long sA,
        const float* __restrict__ Bg, int ldb, long long sB,
        float* __restrict__ C, int ldc, long long sC,
        float alpha, float dval,
        float* __restrict__ C2, const float* __restrict__ bias,
        float* __restrict__ oq, float* __restrict__ okk, float* __restrict__ ov)
{
    constexpr int BK = 16;
    constexpr int WM = BM / WGM, WN = BN / WGN;
    constexpr int MI = WM / 16,  NI = WN / 8;
    constexpr int AI  = (BM * BK) / (256 * 4);
    constexpr int NQ  = BN / 4;
    constexpr int B0I = (BK * BN) / (256 * 4);
    constexpr int B0S = 256 / NQ;
    constexpr int B1I = BN / 64;
    constexpr int BI  = TRANSB ? B1I : B0I;

    __shared__ __align__(16) struct SM {
        uint32_t A[2][BK * BM];
        uint32_t B[2][BK * BN];
        float red[MODE == 7 ? BM * WGN : 1];
    } sm;

    const int bz = blockIdx.z;
    A  += (long long)bz * sA;
    Bg += (long long)bz * sB;
    if (MODE != 5 && MODE != 6) C += (long long)bz * sC;
    if (MODE == 3) C2 += (long long)bz * sC;

    const int tid = threadIdx.x;
    const int rowBase = blockIdx.y * BM;
    const int colBase = blockIdx.x * BN;
    const int w = tid >> 5, lane = tid & 31;
    const int wm = w / WGN, wn = w % WGN;
    const int tm = lane >> 2, lq = lane & 3;

    float acc[MI][NI][4];
#pragma unroll
    for (int mi = 0; mi < MI; mi++)
#pragma unroll
        for (int ni = 0; ni < NI; ni++)
#pragma unroll
            for (int r = 0; r < 4; r++) acc[mi][ni][r] = 0.f;

    const int a_k4 = (tid & 3) * 4;
    const int a_m  = tid >> 2;
    const int b0_n = (tid % NQ) * 4;
    const int b0_k = tid / NQ;
    const int b1_k4 = (tid & 3) * 4;
    const int b1_n  = tid >> 2;

    float4 aReg[AI];
    float4 bReg[BI];

    auto LDG = [&](int kt) {
#pragma unroll
        for (int i = 0; i < AI; i++)
            aReg[i] = *(const float4*)(A + (long long)(rowBase + a_m + 64 * i) * lda + kt + a_k4);
        if (TRANSB == 0) {
#pragma unroll
            for (int i = 0; i < BI; i++)
                bReg[i] = *(const float4*)(Bg + (long long)(kt + b0_k + B0S * i) * ldb + colBase + b0_n);
        } else {
#pragma unroll
            for (int i = 0; i < BI; i++)
                bReg[i] = *(const float4*)(Bg + (long long)(colBase + b1_n + 64 * i) * ldb + kt + b1_k4);
        }
    };
    auto STS = [&](int buf) {
        uint32_t* As = sm.A[buf];
        uint32_t* Bs = sm.B[buf];
#pragma unroll
        for (int i = 0; i < AI; i++) {
            int m = a_m + 64 * i;
            As[(a_k4 + 0) * BM + (m ^ 0 )] = f2tf(aReg[i].x);
            As[(a_k4 + 1) * BM + (m ^ 8 )] = f2tf(aReg[i].y);
            As[(a_k4 + 2) * BM + (m ^ 16)] = f2tf(aReg[i].z);
            As[(a_k4 + 3) * BM + (m ^ 24)] = f2tf(aReg[i].w);
        }
        if (TRANSB == 0) {
#pragma unroll
            for (int i = 0; i < BI; i++) {
                int k = b0_k + B0S * i;
                uint4 u;
                u.x = f2tf(bReg[i].x); u.y = f2tf(bReg[i].y);
                u.z = f2tf(bReg[i].z); u.w = f2tf(bReg[i].w);
                *(uint4*)&Bs[k * BN + (b0_n ^ ((k & 3) << 3))] = u;
            }
        } else {
#pragma unroll
            for (int i = 0; i < BI; i++) {
                int n = b1_n + 64 * i;
                Bs[(b1_k4 + 0) * BN + (n ^ 0 )] = f2tf(bReg[i].x);
                Bs[(b1_k4 + 1) * BN + (n ^ 8 )] = f2tf(bReg[i].y);
                Bs[(b1_k4 + 2) * BN + (n ^ 16)] = f2tf(bReg[i].z);
                Bs[(b1_k4 + 3) * BN + (n ^ 24)] = f2tf(bReg[i].w);
            }
        }
    };

    LDG(0);
    STS(0);
    __syncthreads();

    for (int kt = 0; kt < K; kt += BK) {
        const int cur = (kt / BK) & 1;
        const bool more = (kt + BK) < K;
        if (more) LDG(kt + BK);

        const uint32_t* As = sm.A[cur];
        const uint32_t* Bs = sm.B[cur];
#pragma unroll
        for (int kk = 0; kk < BK; kk += 8) {
            uint32_t af[MI][4], bf[NI][2];
            const int x = lq << 3;
#pragma unroll
            for (int mi = 0; mi < MI; mi++) {
                int m = wm * WM + mi * 16 + tm;
                af[mi][0] = As[(kk + lq)     * BM + ( m      ^ x)];
                af[mi][1] = As[(kk + lq)     * BM + ((m + 8) ^ x)];
                af[mi][2] = As[(kk + lq + 4) * BM + ( m      ^ x)];
                af[mi][3] = As[(kk + lq + 4) * BM + ((m + 8) ^ x)];
            }
#pragma unroll
            for (int ni = 0; ni < NI; ni++) {
                int n = wn * WN + ni * 8 + tm;
                bf[ni][0] = Bs[(kk + lq)     * BN + (n ^ x)];
                bf[ni][1] = Bs[(kk + lq + 4) * BN + (n ^ x)];
            }
#pragma unroll
            for (int mi = 0; mi < MI; mi++)
#pragma unroll
                for (int ni = 0; ni < NI; ni++)
                    mma_tf32(acc[mi][ni], af[mi][0], af[mi][1], af[mi][2], af[mi][3],
                             bf[ni][0], bf[ni][1]);
        }

        if (more) STS(cur ^ 1);
        __syncthreads();
    }

    // -------- epilogue --------
    if (MODE == 7) {
        // WGM==1: each warp's fragments cover ALL BM rows; a row's BN cols span WGN warps.
        // Per thread owns rows: mi*16 + tm (+8), 2*MI rows, NI*2 values each per row.
        float rmax[MI][2], rsum[MI][2];
#pragma unroll
        for (int mi = 0; mi < MI; mi++)
#pragma unroll
            for (int half = 0; half < 2; half++) {
                float m = -3.4e38f;
#pragma unroll
                for (int ni = 0; ni < NI; ni++)
                    m = fmaxf(m, fmaxf(acc[mi][ni][2 * half], acc[mi][ni][2 * half + 1]));
                m = fmaxf(m, __shfl_xor_sync(~0u, m, 1));
                m = fmaxf(m, __shfl_xor_sync(~0u, m, 2));
                rmax[mi][half] = m;
            }
        if (lq == 0) {
#pragma unroll
            for (int mi = 0; mi < MI; mi++)
#pragma unroll
                for (int half = 0; half < 2; half++)
                    sm.red[(mi * 16 + tm + 8 * half) * WGN + w] = rmax[mi][half];
        }
        __syncthreads();
#pragma unroll
        for (int mi = 0; mi < MI; mi++)
#pragma unroll
            for (int half = 0; half < 2; half++) {
                float m = -3.4e38f;
#pragma unroll
                for (int ww = 0; ww < WGN; ww++)
                    m = fmaxf(m, sm.red[(mi * 16 + tm + 8 * half) * WGN + ww]);
                rmax[mi][half] = m;
            }
        __syncthreads();
        // exp & row sums
#pragma unroll
        for (int mi = 0; mi < MI; mi++)
#pragma unroll
            for (int half = 0; half < 2; half++) {
                float s = 0.f;
#pragma unroll
                for (int ni = 0; ni < NI; ni++) {
                    float e0 = __expf(acc[mi][ni][2 * half]     - rmax[mi][half]);
                    float e1 = __expf(acc[mi][ni][2 * half + 1] - rmax[mi][half]);
                    acc[mi][ni][2 * half]     = e0;
                    acc[mi][ni][2 * half + 1] = e1;
                    s += e0 + e1;
                }
                s += __shfl_xor_sync(~0u, s, 1);
                s += __shfl_xor_sync(~0u, s, 2);
                rsum[mi][half] = s;
            }
        if (lq == 0) {
#pragma unroll
            for (int mi = 0; mi < MI; mi++)
#pragma unroll
                for (int half = 0; half < 2; half++)
                    sm.red[(mi * 16 + tm + 8 * half) * WGN + w] = rsum[mi][half];
        }
        __syncthreads();
#pragma unroll
        for (int mi = 0; mi < MI; mi++)
#pragma unroll
            for (int half = 0; half < 2; half++) {
                float s = 0.f;
#pragma unroll
                for (int ww = 0; ww < WGN; ww++)
                    s += sm.red[(mi * 16 + tm + 8 * half) * WGN + ww];
                rsum[mi][half] = 1.f / s;
            }
        // write normalized
#pragma unroll
        for (int mi = 0; mi < MI; mi++) {
#pragma unroll
            for (int ni = 0; ni < NI; ni++) {
                int c = colBase + wn * WN + ni * 8 + 2 * lq;
#pragma unroll
                for (int half = 0; half < 2; half++) {
                    int r = rowBase + mi * 16 + tm + 8 * half;
                    float2 v = make_float2(acc[mi][ni][2 * half] * rsum[mi][half],
                                           acc[mi][ni][2 * half + 1] * rsum[mi][half]);
                    *(float2*)&C[(long long)r * ldc + c] = v;
                }
            }
        }
        return;
    }

#pragma unroll
    for (int mi = 0; mi < MI; mi++) {
        int rBase = rowBase + wm * WM + mi * 16 + tm;
#pragma unroll
        for (int ni = 0; ni < NI; ni++) {
            int c = colBase + wn * WN + ni * 8 + 2 * lq;
#pragma unroll
            for (int half = 0; half < 2; half++) {
                int r = rBase + 8 * half;
                float2 v = make_float2(acc[mi][ni][2 * half], acc[mi][ni][2 * half + 1]);
                if (MODE == 0) {
                    v.x *= alpha; v.y *= alpha;
                    *(float2*)&C[(long long)r * ldc + c] = v;
                } else if (MODE == 2) {
                    v.x = (r == c     ? dval : 0.f) - v.x;
                    v.y = (r == c + 1 ? dval : 0.f) - v.y;
                    *(float2*)&C[(long long)r * ldc + c] = v;
                } else if (MODE == 3) {
                    *(float2*)&C[(long long)r * ldc + c] = v;
                    float2 v2;
                    v2.x = (r == c     ? dval : 0.f) - v.x;
                    v2.y = (r == c + 1 ? dval : 0.f) - v.y;
                    *(float2*)&C2[(long long)r * ldc + c] = v2;
                } else if (MODE == 4) {
                    v.x += bias[c]; v.y += bias[c + 1];
                    *(float2*)&C[(long long)r * ldc + c] = v;
                } else if (MODE == 5) {
                    int b = r >> 12, n = r & 4095;
                    int part = c >> 9, h = (c >> 6) & 7, d = c & 63;
                    if (part == 0) { v.x *= 0.125f; v.y *= 0.125f; }
                    float* dst = (part == 0) ? oq : ((part == 1) ? okk : ov);
                    *(float2*)&dst[((((long long)(b * 8 + h)) << 12) + n) * 64 + d] = v;
                } else { // 6
                    int b = bz >> 3, h = bz & 7;
                    *(float2*)&C[((long long)(b * 4096 + r)) * 512 + h * 64 + c] = v;
                }
            }
        }
    }
}

// ---------------- landmarks ---------------------------------------------------
__global__ void landmarks_kernel(const float* __restrict__ q, const float* __restrict__ k,
                                 float* __restrict__ qlm, float* __restrict__ klm)
{
    int idx = blockIdx.x;          // bh*256 + m
    int d = threadIdx.x;
    long long base = ((long long)idx * 16) * 64 + d;
    float sq = 0.f, sk = 0.f;
#pragma unroll
    for (int j = 0; j < 16; j++) {
        sq += q[base + j * 64];
        sk += k[base + j * 64];
    }
    qlm[(long long)idx * 64 + d] = sq * 0.0625f;
    klm[(long long)idx * 64 + d] = sk * 0.0625f;
}

// ---------------- softmax for 4096-wide rows ------------------------------------
__global__ void softmax4096(float* __restrict__ data)
{
    __shared__ float redm[8], reds[8];
    float4* p = (float4*)(data + ((long long)blockIdx.x << 12));
    int tid = threadIdx.x;
    float4 v[4];
#pragma unroll
    for (int i = 0; i < 4; i++) v[i] = p[tid + 256 * i];
    float m = -3.4e38f;
#pragma unroll
    for (int i = 0; i < 4; i++)
        m = fmaxf(m, fmaxf(fmaxf(v[i].x, v[i].y), fmaxf(v[i].z, v[i].w)));
#pragma unroll
    for (int s = 16; s; s >>= 1) m = fmaxf(m, __shfl_xor_sync(~0u, m, s));
    if ((tid & 31) == 0) redm[tid >> 5] = m;
    __syncthreads();
#pragma unroll
    for (int j = 0; j < 8; j++) m = fmaxf(m, redm[j]);

    float sum = 0.f;
#pragma unroll
    for (int i = 0; i < 4; i++) {
        v[i].x = __expf(v[i].x - m); v[i].y = __expf(v[i].y - m);
        v[i].z = __expf(v[i].z - m); v[i].w = __expf(v[i].w - m);
        sum += v[i].x + v[i].y + v[i].z + v[i].w;
    }
#pragma unroll
    for (int s = 16; s; s >>= 1) sum += __shfl_xor_sync(~0u, sum, s);
    if ((tid & 31) == 0) reds[tid >> 5] = sum;
    __syncthreads();
    sum = 0.f;
#pragma unroll
    for (int j = 0; j < 8; j++) sum += reds[j];
    float inv = 1.f / sum;
#pragma unroll
    for (int i = 0; i < 4; i++) {
        v[i].x *= inv; v[i].y *= inv; v[i].z *= inv; v[i].w *= inv;
        p[tid + 256 * i] = v[i];
    }
}

// ---------------- pinv init ----------------------------------------------------
__global__ void zero_gmax(float* gm) { gm[0] = 0.f; gm[1] = 0.f; }

__global__ void pinv_scales(const float* __restrict__ a, float* gm)
{
    __shared__ float red[256];
    int bh = blockIdx.x, tid = threadIdx.x;
    const float* A = a + ((long long)bh << 16);
    float rs = 0.f;
    for (int j = 0; j < 256; j++) rs += fabsf(A[tid * 256 + j]);
    red[tid] = rs; __syncthreads();
    for (int s = 128; s > 0; s >>= 1) {
        if (tid < s) red[tid] = fmaxf(red[tid], red[tid + s]);
        __syncthreads();
    }
    if (tid == 0) atomicMax((int*)&gm[0], __float_as_int(red[0]));
    __syncthreads();
    float cs = 0.f;
    for (int i = 0; i < 256; i++) cs += fabsf(A[i * 256 + tid]);
    red[tid] = cs; __syncthreads();
    for (int s = 128; s > 0; s >>= 1) {
        if (tid < s) red[tid] = fmaxf(red[tid], red[tid + s]);
        __syncthreads();
    }
    if (tid == 0) atomicMax((int*)&gm[1], __float_as_int(red[0]));
}

__global__ void pinv_init(const float* __restrict__ a, float* __restrict__ z,
                          const float* __restrict__ gm)
{
    long long t = (long long)blockIdx.x * 256 + threadIdx.x;
    int bh = (int)(t >> 16);
    int ij = (int)(t & 65535);
    int i = ij >> 8, j = ij & 255;
    float inv = 1.f / (gm[0] * gm[1]);
    z[((long long)bh << 16) + ij] = a[((long long)bh << 16) + (j << 8) + i] * inv;
}

// ---------------- depthwise conv, accumulates into 'of' layout ------------------
__global__ void conv_add_of(const float* __restrict__ v, const float* __restrict__ w,
                            float* __restrict__ of)
{
    long long t = (long long)blockIdx.x * 256 + threadIdx.x;   // BH*N*DH
    int d = (int)(t & 63);
    long long r = t >> 6;
    int n  = (int)(r & 4095);
    int bh = (int)(r >> 12);
    int h  = bh & 7, b = bh >> 3;
    const float* vp = v + ((long long)bh << 18) + d;
    float s = 0.f;
#pragma unroll
    for (int tp = 0; tp < 33; tp++) {
        int nn = n + tp - 16;
        if (nn >= 0 && nn < 4096)
            s = fmaf(vp[(long long)nn << 6], w[h * 33 + tp], s);
    }
    of[((long long)(b * 4096 + n)) * 512 + h * 64 + d] += s;
}

// ---------------- host orchestration -------------------------------------------
extern "C" void kernel_launch(void* const* d_in, const int* in_sizes, int n_in,
                              void* d_out, int out_size)
{
    const float* x    = (const float*)d_in[0];
    const float* Wqkv = (const float*)d_in[1];
    const float* Wout = (const float*)d_in[2];
    const float* bout = (const float*)d_in[3];
    const float* rk   = (const float*)d_in[4];
    float* yout = (float*)d_out;

    float *q, *k, *v, *qlm, *klm, *s1, *a2, *s3, *z, *z2, *xz, *t1, *t3, *t5,
          *a3v, *zv, *of, *gm;
    cudaGetSymbolAddress((void**)&q,   g_q);
    cudaGetSymbolAddress((void**)&k,   g_k);
    cudaGetSymbolAddress((void**)&v,   g_v);
    cudaGetSymbolAddress((void**)&qlm, g_qlm);
    cudaGetSymbolAddress((void**)&klm, g_klm);
    cudaGetSymbolAddress((void**)&s1,  g_s1);
    cudaGetSymbolAddress((void**)&a2,  g_a2);
    cudaGetSymbolAddress((void**)&s3,  g_s3);
    cudaGetSymbolAddress((void**)&z,   g_z);
    cudaGetSymbolAddress((void**)&z2,  g_z2);
    cudaGetSymbolAddress((void**)&xz,  g_xz);
    cudaGetSymbolAddress((void**)&t1,  g_t1);
    cudaGetSymbolAddress((void**)&t3,  g_t3);
    cudaGetSymbolAddress((void**)&t5,  g_t5);
    cudaGetSymbolAddress((void**)&a3v, g_a3v);
    cudaGetSymbolAddress((void**)&zv,  g_zv);
    cudaGetSymbolAddress((void**)&of,  g_of);
    cudaGetSymbolAddress((void**)&gm,  g_gmax);

    const long long sQ  = (long long)N_ * DH_;   // 262144
    const long long sLM = (long long)M_ * DH_;   // 16384
    const long long sS1 = (long long)N_ * M_;    // 1048576
    const long long sMM = (long long)M_ * M_;    // 65536

    // 1. qkv projection with scatter (q scaled)
    gemm_tc<128,128,2,4,0,5><<<dim3(12, 128, 1), 256>>>(
        512, x, 512, 0, Wqkv, 1536, 0,
        nullptr, 0, 0, 1.f, 0.f, nullptr, nullptr, q, k, v);

    // 2. landmarks
    landmarks_kernel<<<BH_ * M_, DH_>>>(q, k, qlm, klm);

    // 3. attn1 = softmax(q @ klm^T) — fused register-path softmax
    gemm_tc<64,256,1,8,1,7><<<dim3(1, 64, BH_), 256>>>(
        64, q, 64, sQ, klm, 64, sLM,
        s1, 256, sS1, 1.f, 0.f, nullptr, nullptr, nullptr, nullptr, nullptr);

    // 4. attn2 = softmax(qlm @ klm^T) — fused
    gemm_tc<64,256,1,8,1,7><<<dim3(1, 4, BH_), 256>>>(
        64, qlm, 64, sLM, klm, 64, sLM,
        a2, 256, sMM, 1.f, 0.f, nullptr, nullptr, nullptr, nullptr, nullptr);

    // 5. sim3 = qlm @ k^T ; softmax (rows of 4096)
    gemm_tc<128,128,2,4,1,0><<<dim3(32, 2, BH_), 256>>>(
        64, qlm, 64, sLM, k, 64, sQ,
        s3, 4096, (long long)M_ * N_, 1.f, 0.f, nullptr, nullptr, nullptr, nullptr, nullptr);
    softmax4096<<<BH_ * M_, 256>>>(s3);

    // 6. pinv init
    zero_gmax<<<1, 1>>>(gm);
    pinv_scales<<<BH_, 256>>>(a2, gm);
    pinv_init<<<(BH_ * M_ * M_) / 256, 256>>>(a2, z, gm);

    // 7. Newton-Schulz x6
    float* za = z;
    float* zb = z2;
    for (int it = 0; it < 6; it++) {
        gemm_tc<128,128,2,4,0,3><<<dim3(2, 2, BH_), 256>>>(
            256, a2, 256, sMM, za, 256, sMM,
            xz, 256, sMM, 1.f, 7.f, t1, nullptr, nullptr, nullptr, nullptr);
        gemm_tc<128,128,2,4,0,2><<<dim3(2, 2, BH_), 256>>>(
            256, xz, 256, sMM, t1, 256, sMM,
            t3, 256, sMM, 1.f, 15.f, nullptr, nullptr, nullptr, nullptr, nullptr);
        gemm_tc<128,128,2,4,0,2><<<dim3(2, 2, BH_), 256>>>(
            256, xz, 256, sMM, t3, 256, sMM,
            t5, 256, sMM, 1.f, 13.f, nullptr, nullptr, nullptr, nullptr, nullptr);
        gemm_tc<128,128,2,4,0,0><<<dim3(2, 2, BH_), 256>>>(
            256, za, 256, sMM, t5, 256, sMM,
            zb, 256, sMM, 0.25f, 0.f, nullptr, nullptr, nullptr, nullptr, nullptr);
        float* sw = za; za = zb; zb = sw;
    }

    // 8. a3v = attn3 @ v   [256 x 64], K=4096
    gemm_tc<128,64,4,2,0,0><<<dim3(1, 2, BH_), 256>>>(
        4096, s3, 4096, (long long)M_ * N_, v, 64, sQ,
        a3v, 64, sLM, 1.f, 0.f, nullptr, nullptr, nullptr, nullptr, nullptr);

    // 9. zv = z @ a3v   [256 x 64], K=256
    gemm_tc<128,64,4,2,0,0><<<dim3(1, 2, BH_), 256>>>(
        256, za, 256, sMM, a3v, 64, sLM,
        zv, 64, sLM, 1.f, 0.f, nullptr, nullptr, nullptr, nullptr, nullptr);

    // 10. out = attn1 @ zv  -> writes 'of' [b,n,h,d] directly
    gemm_tc<128,64,4,2,0,6><<<dim3(1, 32, BH_), 256>>>(
        256, s1, 256, sS1, zv, 64, sLM,
        of, 0, 0, 1.f, 0.f, nullptr, nullptr, nullptr, nullptr, nullptr);

    // 11. += depthwise conv of v (into 'of' layout)
    conv_add_of<<<(BH_ * N_ * DH_) / 256, 256>>>(v, rk, of);

    // 12. final projection: y = of @ Wout + bout
    gemm_tc<128,128,2,4,0,4><<<dim3(4, 128, 1), 256>>>(
        512, of, 512, 0, Wout, 512, 0,
        yout, 512, 0, 1.f, 0.f, nullptr, bout, nullptr, nullptr, nullptr);
}

// round 5
// speedup vs baseline: 1.3071x; 1.2253x over previous
#include <cuda_runtime.h>
#include <stdint.h>
#include <math.h>

#define B_   4
#define N_   4096
#define DIM_ 512
#define H_   8
#define DH_  64
#define M_   256
#define BH_  32

// ---------------- scratch ----------------------------------------------------
__device__ float g_q  [BH_*N_*DH_];
__device__ float g_k  [BH_*N_*DH_];
__device__ float g_v  [BH_*N_*DH_];
__device__ float g_qlm[BH_*M_*DH_];
__device__ float g_klm[BH_*M_*DH_];
__device__ float g_s1 [BH_*N_*M_];
__device__ float g_a2 [BH_*M_*M_];
__device__ float g_s3 [BH_*M_*N_];
__device__ float g_z  [BH_*M_*M_];
__device__ float g_z2 [BH_*M_*M_];
__device__ float g_xz [BH_*M_*M_];
__device__ float g_t1 [BH_*M_*M_];
__device__ float g_t3 [BH_*M_*M_];
__device__ float g_t5 [BH_*M_*M_];
__device__ float g_a3v[BH_*M_*DH_];
__device__ float g_zv [BH_*M_*DH_];
__device__ float g_of [B_*N_*DIM_];
__device__ float g_part[4*BH_*M_*DH_];
__device__ float g_gmax[2];

// ---------------- tf32 helpers -----------------------------------------------
__device__ __forceinline__ uint32_t f2tf(float f) {
    uint32_t u; asm("cvt.rna.tf32.f32 %0, %1;" : "=r"(u) : "f"(f)); return u;
}

__device__ __forceinline__ void mma_tf32(float c[4],
    uint32_t a0, uint32_t a1, uint32_t a2, uint32_t a3, uint32_t b0, uint32_t b1)
{
    asm("mma.sync.aligned.m16n8k8.row.col.f32.tf32.tf32.f32 "
        "{%0,%1,%2,%3}, {%4,%5,%6,%7}, {%8,%9}, {%0,%1,%2,%3};"
        : "+f"(c[0]), "+f"(c[1]), "+f"(c[2]), "+f"(c[3])
        : "r"(a0), "r"(a1), "r"(a2), "r"(a3), "r"(b0), "r"(b1));
}

__device__ __forceinline__ void cp16(uint32_t smem, const void* gmem) {
    asm volatile("cp.async.cg.shared.global [%0], [%1], 16;\n"
                 :: "r"(smem), "l"(gmem));
}
__device__ __forceinline__ void cp_commit() {
    asm volatile("cp.async.commit_group;\n" ::: "memory");
}
__device__ __forceinline__ void cp_wait0() {
    asm volatile("cp.async.wait_group 0;\n" ::: "memory");
}

// ---------------- tensor-core batched GEMM (cp.async 2-stage) ------------------
// C[bz] = epi( A[bz](MxK,row) @ op(B[bz]) )  — 256 threads, tile BM x BN x 16.
// MODE: 0: alpha*acc   2: dval*I - acc   3: C=acc, C2=dval*I-acc
//       4: acc + bias[col]   5: qkv scatter (q scaled 0.125)
//       6: write [b,n,h,d] 'of' layout
//       7: fused row softmax (requires WGM=1, full row in CTA)
// SPLITK: blockIdx.z = bh*SPLITK + ks ; K = slice length ; C indexed by blockIdx.z
template<int BM, int BN, int WGM, int WGN, int TRANSB, int MODE, int SPLITK = 1>
__global__ void __launch_bounds__(256, 2)
gemm_tc(int K,
        const float* __restrict__ A,  int lda, long long sA,
        const float* __restrict__ Bg, int ldb, long long sB,
        float* __restrict__ C, int ldc, long long sC,
        float alpha, float dval,
        float* __restrict__ C2, const float* __restrict__ bias,
        float* __restrict__ oq, float* __restrict__ okk, float* __restrict__ ov)
{
    constexpr int BK = 16;
    constexpr int WM = BM / WGM, WN = BN / WGN;
    constexpr int MI = WM / 16,  NI = WN / 8;
    constexpr int SAW = BK + 4;                       // padded A row stride (words)
    constexpr int SBW = TRANSB ? (BK + 4) : (BN + 8); // padded B row stride
    constexpr int ASZ = BM * SAW;
    constexpr int BSZ = TRANSB ? (BN * SAW) : (BK * SBW);
    constexpr int A_IT = (BM * 4) / 256;
    constexpr int NB4  = BN / 4;
    constexpr int B0_IT = (BK * NB4) / 256;
    constexpr int B0_KS = 256 / NB4;
    constexpr int B1_IT = (BN * 4) / 256;

    __shared__ __align__(16) float smA[2][ASZ];
    __shared__ __align__(16) float smB[2][BSZ];
    __shared__ float red[MODE == 7 ? BM * WGN : 1];

    const int bz = blockIdx.z;
    const int bh = bz / SPLITK, ks = bz % SPLITK;
    A  += (long long)bh * sA + (long long)ks * K;
    Bg += (long long)bh * sB + (TRANSB ? (long long)ks * K
                                       : (long long)ks * K * ldb);
    if (MODE != 5 && MODE != 6) C += (long long)bz * sC;
    if (MODE == 3) C2 += (long long)bz * sC;

    const int tid = threadIdx.x;
    const int rowBase = blockIdx.y * BM;
    const int colBase = blockIdx.x * BN;
    const int w = tid >> 5, lane = tid & 31;
    const int wm = w / WGN, wn = w % WGN;
    const int tm = lane >> 2, lq = lane & 3;

    float acc[MI][NI][4];
#pragma unroll
    for (int mi = 0; mi < MI; mi++)
#pragma unroll
        for (int ni = 0; ni < NI; ni++)
#pragma unroll
            for (int r = 0; r < 4; r++) acc[mi][ni][r] = 0.f;

    // cp.async thread mapping
    const int ar = tid >> 2, ac = (tid & 3) * 4;          // A: row, k-chunk
    const int b0k = tid / NB4, b0n = (tid % NB4) * 4;     // B !trans
    const int b1r = tid >> 2, b1c = (tid & 3) * 4;        // B trans

    uint32_t sa[2], sb[2];
    sa[0] = (uint32_t)__cvta_generic_to_shared(smA[0]);
    sa[1] = (uint32_t)__cvta_generic_to_shared(smA[1]);
    sb[0] = (uint32_t)__cvta_generic_to_shared(smB[0]);
    sb[1] = (uint32_t)__cvta_generic_to_shared(smB[1]);

    auto LOAD = [&](int kt, int buf) {
#pragma unroll
        for (int i = 0; i < A_IT; i++) {
            int r = ar + 64 * i;
            cp16(sa[buf] + (r * SAW + ac) * 4,
                 A + (long long)(rowBase + r) * lda + kt + ac);
        }
        if (TRANSB == 0) {
#pragma unroll
            for (int i = 0; i < B0_IT; i++) {
                int k = b0k + B0_KS * i;
                cp16(sb[buf] + (k * SBW + b0n) * 4,
                     Bg + (long long)(kt + k) * ldb + colBase + b0n);
            }
        } else {
#pragma unroll
            for (int i = 0; i < B1_IT; i++) {
                int r = b1r + 64 * i;
                cp16(sb[buf] + (r * SAW + b1c) * 4,
                     Bg + (long long)(colBase + r) * ldb + kt + b1c);
            }
        }
        cp_commit();
    };

    LOAD(0, 0);
    const int T = K / BK;

    for (int t = 0; t < T; t++) {
        cp_wait0();
        __syncthreads();
        if (t + 1 < T) LOAD((t + 1) * BK, (t + 1) & 1);

        const float* As = smA[t & 1];
        const float* Bs = smB[t & 1];
#pragma unroll
        for (int kk = 0; kk < BK; kk += 8) {
            const int kq = kk + lq;
            uint32_t af[MI][4], bf[NI][2];
#pragma unroll
            for (int mi = 0; mi < MI; mi++) {
                int m = wm * WM + mi * 16 + tm;
                af[mi][0] = f2tf(As[ m      * SAW + kq]);
                af[mi][1] = f2tf(As[(m + 8) * SAW + kq]);
                af[mi][2] = f2tf(As[ m      * SAW + kq + 4]);
                af[mi][3] = f2tf(As[(m + 8) * SAW + kq + 4]);
            }
#pragma unroll
            for (int ni = 0; ni < NI; ni++) {
                int n = wn * WN + ni * 8 + tm;
                if (TRANSB == 0) {
                    bf[ni][0] = f2tf(Bs[ kq      * SBW + n]);
                    bf[ni][1] = f2tf(Bs[(kq + 4) * SBW + n]);
                } else {
                    bf[ni][0] = f2tf(Bs[n * SAW + kq]);
                    bf[ni][1] = f2tf(Bs[n * SAW + kq + 4]);
                }
            }
#pragma unroll
            for (int mi = 0; mi < MI; mi++)
#pragma unroll
                for (int ni = 0; ni < NI; ni++)
                    mma_tf32(acc[mi][ni], af[mi][0], af[mi][1], af[mi][2], af[mi][3],
                             bf[ni][0], bf[ni][1]);
        }
        __syncthreads();
    }

    // -------- epilogue --------
    if (MODE == 7) {
        float rmax[MI][2], rsum[MI][2];
#pragma unroll
        for (int mi = 0; mi < MI; mi++)
#pragma unroll
            for (int half = 0; half < 2; half++) {
                float m = -3.4e38f;
#pragma unroll
                for (int ni = 0; ni < NI; ni++)
                    m = fmaxf(m, fmaxf(acc[mi][ni][2 * half], acc[mi][ni][2 * half + 1]));
                m = fmaxf(m, __shfl_xor_sync(~0u, m, 1));
                m = fmaxf(m, __shfl_xor_sync(~0u, m, 2));
                rmax[mi][half] = m;
            }
        if (lq == 0) {
#pragma unroll
            for (int mi = 0; mi < MI; mi++)
#pragma unroll
                for (int half = 0; half < 2; half++)
                    red[(mi * 16 + tm + 8 * half) * WGN + w] = rmax[mi][half];
        }
        __syncthreads();
#pragma unroll
        for (int mi = 0; mi < MI; mi++)
#pragma unroll
            for (int half = 0; half < 2; half++) {
                float m = -3.4e38f;
#pragma unroll
                for (int ww = 0; ww < WGN; ww++)
                    m = fmaxf(m, red[(mi * 16 + tm + 8 * half) * WGN + ww]);
                rmax[mi][half] = m;
            }
        __syncthreads();
#pragma unroll
        for (int mi = 0; mi < MI; mi++)
#pragma unroll
            for (int half = 0; half < 2; half++) {
                float s = 0.f;
#pragma unroll
                for (int ni = 0; ni < NI; ni++) {
                    float e0 = __expf(acc[mi][ni][2 * half]     - rmax[mi][half]);
                    float e1 = __expf(acc[mi][ni][2 * half + 1] - rmax[mi][half]);
                    acc[mi][ni][2 * half]     = e0;
                    acc[mi][ni][2 * half + 1] = e1;
                    s += e0 + e1;
                }
                s += __shfl_xor_sync(~0u, s, 1);
                s += __shfl_xor_sync(~0u, s, 2);
                rsum[mi][half] = s;
            }
        if (lq == 0) {
#pragma unroll
            for (int mi = 0; mi < MI; mi++)
#pragma unroll
                for (int half = 0; half < 2; half++)
                    red[(mi * 16 + tm + 8 * half) * WGN + w] = rsum[mi][half];
        }
        __syncthreads();
#pragma unroll
        for (int mi = 0; mi < MI; mi++)
#pragma unroll
            for (int half = 0; half < 2; half++) {
                float s = 0.f;
#pragma unroll
                for (int ww = 0; ww < WGN; ww++)
                    s += red[(mi * 16 + tm + 8 * half) * WGN + ww];
                rsum[mi][half] = 1.f / s;
            }
#pragma unroll
        for (int mi = 0; mi < MI; mi++) {
#pragma unroll
            for (int ni = 0; ni < NI; ni++) {
                int c = colBase + wn * WN + ni * 8 + 2 * lq;
#pragma unroll
                for (int half = 0; half < 2; half++) {
                    int r = rowBase + mi * 16 + tm + 8 * half;
                    float2 v = make_float2(acc[mi][ni][2 * half] * rsum[mi][half],
                                           acc[mi][ni][2 * half + 1] * rsum[mi][half]);
                    *(float2*)&C[(long long)r * ldc + c] = v;
                }
            }
        }
        return;
    }

#pragma unroll
    for (int mi = 0; mi < MI; mi++) {
        int rBase = rowBase + wm * WM + mi * 16 + tm;
#pragma unroll
        for (int ni = 0; ni < NI; ni++) {
            int c = colBase + wn * WN + ni * 8 + 2 * lq;
#pragma unroll
            for (int half = 0; half < 2; half++) {
                int r = rBase + 8 * half;
                float2 v = make_float2(acc[mi][ni][2 * half], acc[mi][ni][2 * half + 1]);
                if (MODE == 0) {
                    v.x *= alpha; v.y *= alpha;
                    *(float2*)&C[(long long)r * ldc + c] = v;
                } else if (MODE == 2) {
                    v.x = (r == c     ? dval : 0.f) - v.x;
                    v.y = (r == c + 1 ? dval : 0.f) - v.y;
                    *(float2*)&C[(long long)r * ldc + c] = v;
                } else if (MODE == 3) {
                    *(float2*)&C[(long long)r * ldc + c] = v;
                    float2 v2;
                    v2.x = (r == c     ? dval : 0.f) - v.x;
                    v2.y = (r == c + 1 ? dval : 0.f) - v.y;
                    *(float2*)&C2[(long long)r * ldc + c] = v2;
                } else if (MODE == 4) {
                    v.x += bias[c]; v.y += bias[c + 1];
                    *(float2*)&C[(long long)r * ldc + c] = v;
                } else if (MODE == 5) {
                    int b = r >> 12, n = r & 4095;
                    int part = c >> 9, h = (c >> 6) & 7, d = c & 63;
                    if (part == 0) { v.x *= 0.125f; v.y *= 0.125f; }
                    float* dst = (part == 0) ? oq : ((part == 1) ? okk : ov);
                    *(float2*)&dst[((((long long)(b * 8 + h)) << 12) + n) * 64 + d] = v;
                } else { // 6
                    int b = bz >> 3, h = bz & 7;
                    *(float2*)&C[((long long)(b * 4096 + r)) * 512 + h * 64 + c] = v;
                }
            }
        }
    }
}

// ---------------- split-K reduction (4 partials) --------------------------------
__global__ void reduce4(const float* __restrict__ p, float* __restrict__ out)
{
    long long t = (long long)blockIdx.x * 256 + threadIdx.x;  // BH*M*DH
    int bh = (int)(t >> 14);            // / (256*64)
    int e  = (int)(t & 16383);
    const float* pp = p + ((long long)bh * 4) * 16384 + e;
    out[t] = pp[0] + pp[16384] + pp[2 * 16384] + pp[3 * 16384];
}

// ---------------- landmarks ---------------------------------------------------
__global__ void landmarks_kernel(const float* __restrict__ q, const float* __restrict__ k,
                                 float* __restrict__ qlm, float* __restrict__ klm)
{
    int idx = blockIdx.x;          // bh*256 + m
    int d = threadIdx.x;
    long long base = ((long long)idx * 16) * 64 + d;
    float sq = 0.f, sk = 0.f;
#pragma unroll
    for (int j = 0; j < 16; j++) {
        sq += q[base + j * 64];
        sk += k[base + j * 64];
    }
    qlm[(long long)idx * 64 + d] = sq * 0.0625f;
    klm[(long long)idx * 64 + d] = sk * 0.0625f;
}

// ---------------- softmax for 4096-wide rows ------------------------------------
__global__ void softmax4096(float* __restrict__ data)
{
    __shared__ float redm[8], reds[8];
    float4* p = (float4*)(data + ((long long)blockIdx.x << 12));
    int tid = threadIdx.x;
    float4 v[4];
#pragma unroll
    for (int i = 0; i < 4; i++) v[i] = p[tid + 256 * i];
    float m = -3.4e38f;
#pragma unroll
    for (int i = 0; i < 4; i++)
        m = fmaxf(m, fmaxf(fmaxf(v[i].x, v[i].y), fmaxf(v[i].z, v[i].w)));
#pragma unroll
    for (int s = 16; s; s >>= 1) m = fmaxf(m, __shfl_xor_sync(~0u, m, s));
    if ((tid & 31) == 0) redm[tid >> 5] = m;
    __syncthreads();
#pragma unroll
    for (int j = 0; j < 8; j++) m = fmaxf(m, redm[j]);

    float sum = 0.f;
#pragma unroll
    for (int i = 0; i < 4; i++) {
        v[i].x = __expf(v[i].x - m); v[i].y = __expf(v[i].y - m);
        v[i].z = __expf(v[i].z - m); v[i].w = __expf(v[i].w - m);
        sum += v[i].x + v[i].y + v[i].z + v[i].w;
    }
#pragma unroll
    for (int s = 16; s; s >>= 1) sum += __shfl_xor_sync(~0u, sum, s);
    if ((tid & 31) == 0) reds[tid >> 5] = sum;
    __syncthreads();
    sum = 0.f;
#pragma unroll
    for (int j = 0; j < 8; j++) sum += reds[j];
    float inv = 1.f / sum;
#pragma unroll
    for (int i = 0; i < 4; i++) {
        v[i].x *= inv; v[i].y *= inv; v[i].z *= inv; v[i].w *= inv;
        p[tid + 256 * i] = v[i];
    }
}

// ---------------- pinv init ----------------------------------------------------
__global__ void zero_gmax(float* gm) { gm[0] = 0.f; gm[1] = 0.f; }

__global__ void pinv_scales(const float* __restrict__ a, float* gm)
{
    __shared__ float red[256];
    int bh = blockIdx.x, tid = threadIdx.x;
    const float* A = a + ((long long)bh << 16);
    float rs = 0.f;
    for (int j = 0; j < 256; j++) rs += fabsf(A[tid * 256 + j]);
    red[tid] = rs; __syncthreads();
    for (int s = 128; s > 0; s >>= 1) {
        if (tid < s) red[tid] = fmaxf(red[tid], red[tid + s]);
        __syncthreads();
    }
    if (tid == 0) atomicMax((int*)&gm[0], __float_as_int(red[0]));
    __syncthreads();
    float cs = 0.f;
    for (int i = 0; i < 256; i++) cs += fabsf(A[i * 256 + tid]);
    red[tid] = cs; __syncthreads();
    for (int s = 128; s > 0; s >>= 1) {
        if (tid < s) red[tid] = fmaxf(red[tid], red[tid + s]);
        __syncthreads();
    }
    if (tid == 0) atomicMax((int*)&gm[1], __float_as_int(red[0]));
}

__global__ void pinv_init(const float* __restrict__ a, float* __restrict__ z,
                          const float* __restrict__ gm)
{
    long long t = (long long)blockIdx.x * 256 + threadIdx.x;
    int bh = (int)(t >> 16);
    int ij = (int)(t & 65535);
    int i = ij >> 8, j = ij & 255;
    float inv = 1.f / (gm[0] * gm[1]);
    z[((long long)bh << 16) + ij] = a[((long long)bh << 16) + (j << 8) + i] * inv;
}

// ---------------- depthwise conv, accumulates into 'of' layout ------------------
__global__ void conv_add_of(const float* __restrict__ v, const float* __restrict__ w,
                            float* __restrict__ of)
{
    long long t = (long long)blockIdx.x * 256 + threadIdx.x;   // BH*N*DH
    int d = (int)(t & 63);
    long long r = t >> 6;
    int n  = (int)(r & 4095);
    int bh = (int)(r >> 12);
    int h  = bh & 7, b = bh >> 3;
    const float* vp = v + ((long long)bh << 18) + d;
    float s = 0.f;
#pragma unroll
    for (int tp = 0; tp < 33; tp++) {
        int nn = n + tp - 16;
        if (nn >= 0 && nn < 4096)
            s = fmaf(vp[(long long)nn << 6], w[h * 33 + tp], s);
    }
    of[((long long)(b * 4096 + n)) * 512 + h * 64 + d] += s;
}

// ---------------- host orchestration -------------------------------------------
extern "C" void kernel_launch(void* const* d_in, const int* in_sizes, int n_in,
                              void* d_out, int out_size)
{
    const float* x    = (const float*)d_in[0];
    const float* Wqkv = (const float*)d_in[1];
    const float* Wout = (const float*)d_in[2];
    const float* bout = (const float*)d_in[3];
    const float* rk   = (const float*)d_in[4];
    float* yout = (float*)d_out;

    float *q, *k, *v, *qlm, *klm, *s1, *a2, *s3, *z, *z2, *xz, *t1, *t3, *t5,
          *a3v, *zv, *of, *part, *gm;
    cudaGetSymbolAddress((void**)&q,   g_q);
    cudaGetSymbolAddress((void**)&k,   g_k);
    cudaGetSymbolAddress((void**)&v,   g_v);
    cudaGetSymbolAddress((void**)&qlm, g_qlm);
    cudaGetSymbolAddress((void**)&klm, g_klm);
    cudaGetSymbolAddress((void**)&s1,  g_s1);
    cudaGetSymbolAddress((void**)&a2,  g_a2);
    cudaGetSymbolAddress((void**)&s3,  g_s3);
    cudaGetSymbolAddress((void**)&z,   g_z);
    cudaGetSymbolAddress((void**)&z2,  g_z2);
    cudaGetSymbolAddress((void**)&xz,  g_xz);
    cudaGetSymbolAddress((void**)&t1,  g_t1);
    cudaGetSymbolAddress((void**)&t3,  g_t3);
    cudaGetSymbolAddress((void**)&t5,  g_t5);
    cudaGetSymbolAddress((void**)&a3v, g_a3v);
    cudaGetSymbolAddress((void**)&zv,  g_zv);
    cudaGetSymbolAddress((void**)&of,  g_of);
    cudaGetSymbolAddress((void**)&part,g_part);
    cudaGetSymbolAddress((void**)&gm,  g_gmax);

    const long long sQ  = (long long)N_ * DH_;   // 262144
    const long long sLM = (long long)M_ * DH_;   // 16384
    const long long sS1 = (long long)N_ * M_;    // 1048576
    const long long sMM = (long long)M_ * M_;    // 65536

    // 1. qkv projection with scatter (q scaled)
    gemm_tc<128,128,2,4,0,5><<<dim3(12, 128, 1), 256>>>(
        512, x, 512, 0, Wqkv, 1536, 0,
        nullptr, 0, 0, 1.f, 0.f, nullptr, nullptr, q, k, v);

    // 2. landmarks
    landmarks_kernel<<<BH_ * M_, DH_>>>(q, k, qlm, klm);

    // 3. attn1 = softmax(q @ klm^T) — fused register-path softmax
    gemm_tc<64,256,1,8,1,7><<<dim3(1, 64, BH_), 256>>>(
        64, q, 64, sQ, klm, 64, sLM,
        s1, 256, sS1, 1.f, 0.f, nullptr, nullptr, nullptr, nullptr, nullptr);

    // 4. attn2 = softmax(qlm @ klm^T) — fused
    gemm_tc<64,256,1,8,1,7><<<dim3(1, 4, BH_), 256>>>(
        64, qlm, 64, sLM, klm, 64, sLM,
        a2, 256, sMM, 1.f, 0.f, nullptr, nullptr, nullptr, nullptr, nullptr);

    // 5. sim3 = qlm @ k^T ; softmax (rows of 4096)
    gemm_tc<128,128,2,4,1,0><<<dim3(32, 2, BH_), 256>>>(
        64, qlm, 64, sLM, k, 64, sQ,
        s3, 4096, (long long)M_ * N_, 1.f, 0.f, nullptr, nullptr, nullptr, nullptr, nullptr);
    softmax4096<<<BH_ * M_, 256>>>(s3);

    // 6. pinv init
    zero_gmax<<<1, 1>>>(gm);
    pinv_scales<<<BH_, 256>>>(a2, gm);
    pinv_init<<<(BH_ * M_ * M_) / 256, 256>>>(a2, z, gm);

    // 7. Newton-Schulz x6
    float* za = z;
    float* zb = z2;
    for (int it = 0; it < 6; it++) {
        gemm_tc<128,128,2,4,0,3><<<dim3(2, 2, BH_), 256>>>(
            256, a2, 256, sMM, za, 256, sMM,
            xz, 256, sMM, 1.f, 7.f, t1, nullptr, nullptr, nullptr, nullptr);
        gemm_tc<128,128,2,4,0,2><<<dim3(2, 2, BH_), 256>>>(
            256, xz, 256, sMM, t1, 256, sMM,
            t3, 256, sMM, 1.f, 15.f, nullptr, nullptr, nullptr, nullptr, nullptr);
        gemm_tc<128,128,2,4,0,2><<<dim3(2, 2, BH_), 256>>>(
            256, xz, 256, sMM, t3, 256, sMM,
            t5, 256, sMM, 1.f, 13.f, nullptr, nullptr, nullptr, nullptr, nullptr);
        gemm_tc<128,128,2,4,0,0><<<dim3(2, 2, BH_), 256>>>(
            256, za, 256, sMM, t5, 256, sMM,
            zb, 256, sMM, 0.25f, 0.f, nullptr, nullptr, nullptr, nullptr, nullptr);
        float* sw = za; za = zb; zb = sw;
    }

    // 8. a3v = attn3 @ v  — split-K x4: partials then reduce
    gemm_tc<128,64,4,2,0,0,4><<<dim3(1, 2, BH_ * 4), 256>>>(
        1024, s3, 4096, (long long)M_ * N_, v, 64, sQ,
        part, 64, sLM, 1.f, 0.f, nullptr, nullptr, nullptr, nullptr, nullptr);
    reduce4<<<(BH_ * M_ * DH_) / 256, 256>>>(part, a3v);

    // 9. zv = z @ a3v   [256 x 64], K=256
    gemm_tc<128,64,4,2,0,0><<<dim3(1, 2, BH_), 256>>>(
        256, za, 256, sMM, a3v, 64, sLM,
        zv, 64, sLM, 1.f, 0.f, nullptr, nullptr, nullptr, nullptr, nullptr);

    // 10. out = attn1 @ zv  -> writes 'of' [b,n,h,d] directly
    gemm_tc<128,64,4,2,0,6><<<dim3(1, 32, BH_), 256>>>(
        256, s1, 256, sS1, zv, 64, sLM,
        of, 0, 0, 1.f, 0.f, nullptr, nullptr, nullptr, nullptr, nullptr);

    // 11. += depthwise conv of v (into 'of' layout)
    conv_add_of<<<(BH_ * N_ * DH_) / 256, 256>>>(v, rk, of);

    // 12. final projection: y = of @ Wout + bout
    gemm_tc<128,128,2,4,0,4><<<dim3(4, 128, 1), 256>>>(
        512, of, 512, 0, Wout, 512, 0,
        yout, 512, 0, 1.f, 0.f, nullptr, bout, nullptr, nullptr, nullptr);
}

// round 6
// speedup vs baseline: 1.3091x; 1.0016x over previous
#include <cuda_runtime.h>
#include <stdint.h>
#include <math.h>

#define B_   4
#define N_   4096
#define DIM_ 512
#define H_   8
#define DH_  64
#define M_   256
#define BH_  32

// ---------------- scratch ----------------------------------------------------
__device__ float g_x  [B_*N_*DIM_];        // tf32-rounded copy of x
__device__ float g_wq [DIM_*3*H_*DH_];     // rounded Wqkv
__device__ float g_wo [H_*DH_*DIM_];       // rounded Wout
__device__ float g_q  [BH_*N_*DH_];
__device__ float g_k  [BH_*N_*DH_];
__device__ float g_v  [BH_*N_*DH_];
__device__ float g_qlm[BH_*M_*DH_];
__device__ float g_klm[BH_*M_*DH_];
__device__ float g_s1 [BH_*N_*M_];
__device__ float g_a2 [BH_*M_*M_];
__device__ float g_s3 [BH_*M_*N_];
__device__ float g_z  [BH_*M_*M_];
__device__ float g_z2 [BH_*M_*M_];
__device__ float g_xz [BH_*M_*M_];
__device__ float g_t1 [BH_*M_*M_];
__device__ float g_t3 [BH_*M_*M_];
__device__ float g_t5 [BH_*M_*M_];
__device__ float g_a3v[BH_*M_*DH_];
__device__ float g_zv [BH_*M_*DH_];
__device__ float g_of [B_*N_*DIM_];
__device__ float g_part[4*BH_*M_*DH_];
__device__ float g_gmax[2];

// ---------------- tf32 helpers -----------------------------------------------
__device__ __forceinline__ uint32_t f2tf(float f) {
    uint32_t u; asm("cvt.rna.tf32.f32 %0, %1;" : "=r"(u) : "f"(f)); return u;
}
__device__ __forceinline__ float rtf(float f) { return __uint_as_float(f2tf(f)); }

__device__ __forceinline__ void mma_tf32(float c[4],
    uint32_t a0, uint32_t a1, uint32_t a2, uint32_t a3, uint32_t b0, uint32_t b1)
{
    asm("mma.sync.aligned.m16n8k8.row.col.f32.tf32.tf32.f32 "
        "{%0,%1,%2,%3}, {%4,%5,%6,%7}, {%8,%9}, {%0,%1,%2,%3};"
        : "+f"(c[0]), "+f"(c[1]), "+f"(c[2]), "+f"(c[3])
        : "r"(a0), "r"(a1), "r"(a2), "r"(a3), "r"(b0), "r"(b1));
}

__device__ __forceinline__ void cp16(uint32_t smem, const void* gmem) {
    asm volatile("cp.async.cg.shared.global [%0], [%1], 16;\n"
                 :: "r"(smem), "l"(gmem));
}
__device__ __forceinline__ void cp_commit() {
    asm volatile("cp.async.commit_group;\n" ::: "memory");
}
__device__ __forceinline__ void cp_wait0() {
    asm volatile("cp.async.wait_group 0;\n" ::: "memory");
}

// ---------------- pre-round inputs ---------------------------------------------
__global__ void round_copy(const float* __restrict__ in, float* __restrict__ out)
{
    long long t = (long long)blockIdx.x * 256 + threadIdx.x;
    out[t] = rtf(in[t]);
}

// ---------------- tensor-core batched GEMM (cp.async 2-stage) ------------------
// All MMA-consumed inputs are pre-rounded tf32 — mainloop passes raw bits (no cvt).
// MODE: 0: alpha*acc   2: dval*I - acc   3: C=acc, C2=dval*I-acc
//       4: acc + bias[col] (final output, NOT rounded)
//       5: qkv scatter (q scaled 0.125)   6: write [b,n,h,d] 'of' layout
//       7: fused row softmax (requires WGM=1, full row in CTA)
// RND: round stores to tf32 (modes 0/2/3); modes 5/6/7 always round, 4 never.
template<int BM, int BN, int WGM, int WGN, int TRANSB, int MODE, int SPLITK = 1, int RND = 1>
__global__ void __launch_bounds__(256, 2)
gemm_tc(int K,
        const float* __restrict__ A,  int lda, long long sA,
        const float* __restrict__ Bg, int ldb, long long sB,
        float* __restrict__ C, int ldc, long long sC,
        float alpha, float dval,
        float* __restrict__ C2, const float* __restrict__ bias,
        float* __restrict__ oq, float* __restrict__ okk, float* __restrict__ ov)
{
    constexpr int BK = 16;
    constexpr int WM = BM / WGM, WN = BN / WGN;
    constexpr int MI = WM / 16,  NI = WN / 8;
    constexpr int SAW = BK + 4;
    constexpr int SBW = TRANSB ? (BK + 4) : (BN + 8);
    constexpr int ASZ = BM * SAW;
    constexpr int BSZ = TRANSB ? (BN * SAW) : (BK * SBW);
    constexpr int A_IT = (BM * 4) / 256;
    constexpr int NB4  = BN / 4;
    constexpr int B0_IT = (BK * NB4) / 256;
    constexpr int B0_KS = 256 / NB4;
    constexpr int B1_IT = (BN * 4) / 256;

    __shared__ __align__(16) float smA[2][ASZ];
    __shared__ __align__(16) float smB[2][BSZ];
    __shared__ float red[MODE == 7 ? BM * WGN : 1];

    const int bz = blockIdx.z;
    const int bh = bz / SPLITK, ks = bz % SPLITK;
    A  += (long long)bh * sA + (long long)ks * K;
    Bg += (long long)bh * sB + (TRANSB ? (long long)ks * K
                                       : (long long)ks * K * ldb);
    if (MODE != 5 && MODE != 6) C += (long long)bz * sC;
    if (MODE == 3) C2 += (long long)bz * sC;

    const int tid = threadIdx.x;
    const int rowBase = blockIdx.y * BM;
    const int colBase = blockIdx.x * BN;
    const int w = tid >> 5, lane = tid & 31;
    const int wm = w / WGN, wn = w % WGN;
    const int tm = lane >> 2, lq = lane & 3;

    float acc[MI][NI][4];
#pragma unroll
    for (int mi = 0; mi < MI; mi++)
#pragma unroll
        for (int ni = 0; ni < NI; ni++)
#pragma unroll
            for (int r = 0; r < 4; r++) acc[mi][ni][r] = 0.f;

    const int ar = tid >> 2, ac = (tid & 3) * 4;
    const int b0k = tid / NB4, b0n = (tid % NB4) * 4;
    const int b1r = tid >> 2, b1c = (tid & 3) * 4;

    uint32_t sa[2], sb[2];
    sa[0] = (uint32_t)__cvta_generic_to_shared(smA[0]);
    sa[1] = (uint32_t)__cvta_generic_to_shared(smA[1]);
    sb[0] = (uint32_t)__cvta_generic_to_shared(smB[0]);
    sb[1] = (uint32_t)__cvta_generic_to_shared(smB[1]);

    auto LOAD = [&](int kt, int buf) {
#pragma unroll
        for (int i = 0; i < A_IT; i++) {
            int r = ar + 64 * i;
            cp16(sa[buf] + (r * SAW + ac) * 4,
                 A + (long long)(rowBase + r) * lda + kt + ac);
        }
        if (TRANSB == 0) {
#pragma unroll
            for (int i = 0; i < B0_IT; i++) {
                int k = b0k + B0_KS * i;
                cp16(sb[buf] + (k * SBW + b0n) * 4,
                     Bg + (long long)(kt + k) * ldb + colBase + b0n);
            }
        } else {
#pragma unroll
            for (int i = 0; i < B1_IT; i++) {
                int r = b1r + 64 * i;
                cp16(sb[buf] + (r * SAW + b1c) * 4,
                     Bg + (long long)(colBase + r) * ldb + kt + b1c);
            }
        }
        cp_commit();
    };

    LOAD(0, 0);
    const int T = K / BK;

    for (int t = 0; t < T; t++) {
        cp_wait0();
        __syncthreads();
        if (t + 1 < T) LOAD((t + 1) * BK, (t + 1) & 1);

        const float* As = smA[t & 1];
        const float* Bs = smB[t & 1];
#pragma unroll
        for (int kk = 0; kk < BK; kk += 8) {
            const int kq = kk + lq;
            uint32_t af[MI][4], bf[NI][2];
#pragma unroll
            for (int mi = 0; mi < MI; mi++) {
                int m = wm * WM + mi * 16 + tm;
                af[mi][0] = __float_as_uint(As[ m      * SAW + kq]);
                af[mi][1] = __float_as_uint(As[(m + 8) * SAW + kq]);
                af[mi][2] = __float_as_uint(As[ m      * SAW + kq + 4]);
                af[mi][3] = __float_as_uint(As[(m + 8) * SAW + kq + 4]);
            }
#pragma unroll
            for (int ni = 0; ni < NI; ni++) {
                int n = wn * WN + ni * 8 + tm;
                if (TRANSB == 0) {
                    bf[ni][0] = __float_as_uint(Bs[ kq      * SBW + n]);
                    bf[ni][1] = __float_as_uint(Bs[(kq + 4) * SBW + n]);
                } else {
                    bf[ni][0] = __float_as_uint(Bs[n * SAW + kq]);
                    bf[ni][1] = __float_as_uint(Bs[n * SAW + kq + 4]);
                }
            }
#pragma unroll
            for (int mi = 0; mi < MI; mi++)
#pragma unroll
                for (int ni = 0; ni < NI; ni++)
                    mma_tf32(acc[mi][ni], af[mi][0], af[mi][1], af[mi][2], af[mi][3],
                             bf[ni][0], bf[ni][1]);
        }
        __syncthreads();
    }

    // -------- epilogue --------
    if (MODE == 7) {
        float rmax[MI][2], rsum[MI][2];
#pragma unroll
        for (int mi = 0; mi < MI; mi++)
#pragma unroll
            for (int half = 0; half < 2; half++) {
                float m = -3.4e38f;
#pragma unroll
                for (int ni = 0; ni < NI; ni++)
                    m = fmaxf(m, fmaxf(acc[mi][ni][2 * half], acc[mi][ni][2 * half + 1]));
                m = fmaxf(m, __shfl_xor_sync(~0u, m, 1));
                m = fmaxf(m, __shfl_xor_sync(~0u, m, 2));
                rmax[mi][half] = m;
            }
        if (lq == 0) {
#pragma unroll
            for (int mi = 0; mi < MI; mi++)
#pragma unroll
                for (int half = 0; half < 2; half++)
                    red[(mi * 16 + tm + 8 * half) * WGN + w] = rmax[mi][half];
        }
        __syncthreads();
#pragma unroll
        for (int mi = 0; mi < MI; mi++)
#pragma unroll
            for (int half = 0; half < 2; half++) {
                float m = -3.4e38f;
#pragma unroll
                for (int ww = 0; ww < WGN; ww++)
                    m = fmaxf(m, red[(mi * 16 + tm + 8 * half) * WGN + ww]);
                rmax[mi][half] = m;
            }
        __syncthreads();
#pragma unroll
        for (int mi = 0; mi < MI; mi++)
#pragma unroll
            for (int half = 0; half < 2; half++) {
                float s = 0.f;
#pragma unroll
                for (int ni = 0; ni < NI; ni++) {
                    float e0 = __expf(acc[mi][ni][2 * half]     - rmax[mi][half]);
                    float e1 = __expf(acc[mi][ni][2 * half + 1] - rmax[mi][half]);
                    acc[mi][ni][2 * half]     = e0;
                    acc[mi][ni][2 * half + 1] = e1;
                    s += e0 + e1;
                }
                s += __shfl_xor_sync(~0u, s, 1);
                s += __shfl_xor_sync(~0u, s, 2);
                rsum[mi][half] = s;
            }
        if (lq == 0) {
#pragma unroll
            for (int mi = 0; mi < MI; mi++)
#pragma unroll
                for (int half = 0; half < 2; half++)
                    red[(mi * 16 + tm + 8 * half) * WGN + w] = rsum[mi][half];
        }
        __syncthreads();
#pragma unroll
        for (int mi = 0; mi < MI; mi++)
#pragma unroll
            for (int half = 0; half < 2; half++) {
                float s = 0.f;
#pragma unroll
                for (int ww = 0; ww < WGN; ww++)
                    s += red[(mi * 16 + tm + 8 * half) * WGN + ww];
                rsum[mi][half] = 1.f / s;
            }
#pragma unroll
        for (int mi = 0; mi < MI; mi++) {
#pragma unroll
            for (int ni = 0; ni < NI; ni++) {
                int c = colBase + wn * WN + ni * 8 + 2 * lq;
#pragma unroll
                for (int half = 0; half < 2; half++) {
                    int r = rowBase + mi * 16 + tm + 8 * half;
                    float2 v = make_float2(rtf(acc[mi][ni][2 * half] * rsum[mi][half]),
                                           rtf(acc[mi][ni][2 * half + 1] * rsum[mi][half]));
                    *(float2*)&C[(long long)r * ldc + c] = v;
                }
            }
        }
        return;
    }

#pragma unroll
    for (int mi = 0; mi < MI; mi++) {
        int rBase = rowBase + wm * WM + mi * 16 + tm;
#pragma unroll
        for (int ni = 0; ni < NI; ni++) {
            int c = colBase + wn * WN + ni * 8 + 2 * lq;
#pragma unroll
            for (int half = 0; half < 2; half++) {
                int r = rBase + 8 * half;
                float2 v = make_float2(acc[mi][ni][2 * half], acc[mi][ni][2 * half + 1]);
                if (MODE == 0) {
                    v.x *= alpha; v.y *= alpha;
                    if (RND) { v.x = rtf(v.x); v.y = rtf(v.y); }
                    *(float2*)&C[(long long)r * ldc + c] = v;
                } else if (MODE == 2) {
                    v.x = (r == c     ? dval : 0.f) - v.x;
                    v.y = (r == c + 1 ? dval : 0.f) - v.y;
                    if (RND) { v.x = rtf(v.x); v.y = rtf(v.y); }
                    *(float2*)&C[(long long)r * ldc + c] = v;
                } else if (MODE == 3) {
                    float2 v1 = v;
                    if (RND) { v1.x = rtf(v1.x); v1.y = rtf(v1.y); }
                    *(float2*)&C[(long long)r * ldc + c] = v1;
                    float2 v2;
                    v2.x = (r == c     ? dval : 0.f) - v.x;
                    v2.y = (r == c + 1 ? dval : 0.f) - v.y;
                    if (RND) { v2.x = rtf(v2.x); v2.y = rtf(v2.y); }
                    *(float2*)&C2[(long long)r * ldc + c] = v2;
                } else if (MODE == 4) {
                    v.x += bias[c]; v.y += bias[c + 1];
                    *(float2*)&C[(long long)r * ldc + c] = v;
                } else if (MODE == 5) {
                    int b = r >> 12, n = r & 4095;
                    int part = c >> 9, h = (c >> 6) & 7, d = c & 63;
                    if (part == 0) { v.x *= 0.125f; v.y *= 0.125f; }
                    v.x = rtf(v.x); v.y = rtf(v.y);
                    float* dst = (part == 0) ? oq : ((part == 1) ? okk : ov);
                    *(float2*)&dst[((((long long)(b * 8 + h)) << 12) + n) * 64 + d] = v;
                } else { // 6
                    int b = bz >> 3, h = bz & 7;
                    v.x = rtf(v.x); v.y = rtf(v.y);
                    *(float2*)&C[((long long)(b * 4096 + r)) * 512 + h * 64 + c] = v;
                }
            }
        }
    }
}

// ---------------- split-K reduction (4 partials) --------------------------------
__global__ void reduce4(const float* __restrict__ p, float* __restrict__ out)
{
    long long t = (long long)blockIdx.x * 256 + threadIdx.x;  // BH*M*DH
    int bh = (int)(t >> 14);
    int e  = (int)(t & 16383);
    const float* pp = p + ((long long)bh * 4) * 16384 + e;
    out[t] = rtf(pp[0] + pp[16384] + pp[2 * 16384] + pp[3 * 16384]);
}

// ---------------- landmarks ---------------------------------------------------
__global__ void landmarks_kernel(const float* __restrict__ q, const float* __restrict__ k,
                                 float* __restrict__ qlm, float* __restrict__ klm)
{
    int idx = blockIdx.x;          // bh*256 + m
    int d = threadIdx.x;
    long long base = ((long long)idx * 16) * 64 + d;
    float sq = 0.f, sk = 0.f;
#pragma unroll
    for (int j = 0; j < 16; j++) {
        sq += q[base + j * 64];
        sk += k[base + j * 64];
    }
    qlm[(long long)idx * 64 + d] = rtf(sq * 0.0625f);
    klm[(long long)idx * 64 + d] = rtf(sk * 0.0625f);
}

// ---------------- softmax for 4096-wide rows (writes rounded) -------------------
__global__ void softmax4096(float* __restrict__ data)
{
    __shared__ float redm[8], reds[8];
    float4* p = (float4*)(data + ((long long)blockIdx.x << 12));
    int tid = threadIdx.x;
    float4 v[4];
#pragma unroll
    for (int i = 0; i < 4; i++) v[i] = p[tid + 256 * i];
    float m = -3.4e38f;
#pragma unroll
    for (int i = 0; i < 4; i++)
        m = fmaxf(m, fmaxf(fmaxf(v[i].x, v[i].y), fmaxf(v[i].z, v[i].w)));
#pragma unroll
    for (int s = 16; s; s >>= 1) m = fmaxf(m, __shfl_xor_sync(~0u, m, s));
    if ((tid & 31) == 0) redm[tid >> 5] = m;
    __syncthreads();
#pragma unroll
    for (int j = 0; j < 8; j++) m = fmaxf(m, redm[j]);

    float sum = 0.f;
#pragma unroll
    for (int i = 0; i < 4; i++) {
        v[i].x = __expf(v[i].x - m); v[i].y = __expf(v[i].y - m);
        v[i].z = __expf(v[i].z - m); v[i].w = __expf(v[i].w - m);
        sum += v[i].x + v[i].y + v[i].z + v[i].w;
    }
#pragma unroll
    for (int s = 16; s; s >>= 1) sum += __shfl_xor_sync(~0u, sum, s);
    if ((tid & 31) == 0) reds[tid >> 5] = sum;
    __syncthreads();
    sum = 0.f;
#pragma unroll
    for (int j = 0; j < 8; j++) sum += reds[j];
    float inv = 1.f / sum;
#pragma unroll
    for (int i = 0; i < 4; i++) {
        v[i].x = rtf(v[i].x * inv); v[i].y = rtf(v[i].y * inv);
        v[i].z = rtf(v[i].z * inv); v[i].w = rtf(v[i].w * inv);
        p[tid + 256 * i] = v[i];
    }
}

// ---------------- pinv init ----------------------------------------------------
__global__ void zero_gmax(float* gm) { gm[0] = 0.f; gm[1] = 0.f; }

__global__ void pinv_scales(const float* __restrict__ a, float* gm)
{
    __shared__ float red[256];
    int bh = blockIdx.x, tid = threadIdx.x;
    const float* A = a + ((long long)bh << 16);
    float rs = 0.f;
    for (int j = 0; j < 256; j++) rs += fabsf(A[tid * 256 + j]);
    red[tid] = rs; __syncthreads();
    for (int s = 128; s > 0; s >>= 1) {
        if (tid < s) red[tid] = fmaxf(red[tid], red[tid + s]);
        __syncthreads();
    }
    if (tid == 0) atomicMax((int*)&gm[0], __float_as_int(red[0]));
    __syncthreads();
    float cs = 0.f;
    for (int i = 0; i < 256; i++) cs += fabsf(A[i * 256 + tid]);
    red[tid] = cs; __syncthreads();
    for (int s = 128; s > 0; s >>= 1) {
        if (tid < s) red[tid] = fmaxf(red[tid], red[tid + s]);
        __syncthreads();
    }
    if (tid == 0) atomicMax((int*)&gm[1], __float_as_int(red[0]));
}

__global__ void pinv_init(const float* __restrict__ a, float* __restrict__ z,
                          const float* __restrict__ gm)
{
    long long t = (long long)blockIdx.x * 256 + threadIdx.x;
    int bh = (int)(t >> 16);
    int ij = (int)(t & 65535);
    int i = ij >> 8, j = ij & 255;
    float inv = 1.f / (gm[0] * gm[1]);
    z[((long long)bh << 16) + ij] = rtf(a[((long long)bh << 16) + (j << 8) + i] * inv);
}

// ---------------- depthwise conv, accumulates into 'of' layout ------------------
__global__ void conv_add_of(const float* __restrict__ v, const float* __restrict__ w,
                            float* __restrict__ of)
{
    long long t = (long long)blockIdx.x * 256 + threadIdx.x;   // BH*N*DH
    int d = (int)(t & 63);
    long long r = t >> 6;
    int n  = (int)(r & 4095);
    int bh = (int)(r >> 12);
    int h  = bh & 7, b = bh >> 3;
    const float* vp = v + ((long long)bh << 18) + d;
    float s = 0.f;
#pragma unroll
    for (int tp = 0; tp < 33; tp++) {
        int nn = n + tp - 16;
        if (nn >= 0 && nn < 4096)
            s = fmaf(vp[(long long)nn << 6], w[h * 33 + tp], s);
    }
    long long oidx = ((long long)(b * 4096 + n)) * 512 + h * 64 + d;
    of[oidx] = rtf(of[oidx] + s);
}

// ---------------- host orchestration -------------------------------------------
extern "C" void kernel_launch(void* const* d_in, const int* in_sizes, int n_in,
                              void* d_out, int out_size)
{
    const float* x    = (const float*)d_in[0];
    const float* Wqkv = (const float*)d_in[1];
    const float* Wout = (const float*)d_in[2];
    const float* bout = (const float*)d_in[3];
    const float* rk   = (const float*)d_in[4];
    float* yout = (float*)d_out;

    float *xr, *wq, *wo, *q, *k, *v, *qlm, *klm, *s1, *a2, *s3, *z, *z2, *xz,
          *t1, *t3, *t5, *a3v, *zv, *of, *part, *gm;
    cudaGetSymbolAddress((void**)&xr,  g_x);
    cudaGetSymbolAddress((void**)&wq,  g_wq);
    cudaGetSymbolAddress((void**)&wo,  g_wo);
    cudaGetSymbolAddress((void**)&q,   g_q);
    cudaGetSymbolAddress((void**)&k,   g_k);
    cudaGetSymbolAddress((void**)&v,   g_v);
    cudaGetSymbolAddress((void**)&qlm, g_qlm);
    cudaGetSymbolAddress((void**)&klm, g_klm);
    cudaGetSymbolAddress((void**)&s1,  g_s1);
    cudaGetSymbolAddress((void**)&a2,  g_a2);
    cudaGetSymbolAddress((void**)&s3,  g_s3);
    cudaGetSymbolAddress((void**)&z,   g_z);
    cudaGetSymbolAddress((void**)&z2,  g_z2);
    cudaGetSymbolAddress((void**)&xz,  g_xz);
    cudaGetSymbolAddress((void**)&t1,  g_t1);
    cudaGetSymbolAddress((void**)&t3,  g_t3);
    cudaGetSymbolAddress((void**)&t5,  g_t5);
    cudaGetSymbolAddress((void**)&a3v, g_a3v);
    cudaGetSymbolAddress((void**)&zv,  g_zv);
    cudaGetSymbolAddress((void**)&of,  g_of);
    cudaGetSymbolAddress((void**)&part,g_part);
    cudaGetSymbolAddress((void**)&gm,  g_gmax);

    const long long sQ  = (long long)N_ * DH_;
    const long long sLM = (long long)M_ * DH_;
    const long long sS1 = (long long)N_ * M_;
    const long long sMM = (long long)M_ * M_;

    // 0. pre-round harness inputs to tf32
    round_copy<<<(B_*N_*DIM_) / 256, 256>>>(x, xr);
    round_copy<<<(DIM_*3*H_*DH_) / 256, 256>>>(Wqkv, wq);
    round_copy<<<(H_*DH_*DIM_) / 256, 256>>>(Wout, wo);

    // 1. qkv projection with scatter (q scaled)
    gemm_tc<128,128,2,4,0,5><<<dim3(12, 128, 1), 256>>>(
        512, xr, 512, 0, wq, 1536, 0,
        nullptr, 0, 0, 1.f, 0.f, nullptr, nullptr, q, k, v);

    // 2. landmarks
    landmarks_kernel<<<BH_ * M_, DH_>>>(q, k, qlm, klm);

    // 3. attn1 = softmax(q @ klm^T) — fused register-path softmax
    gemm_tc<64,256,1,8,1,7><<<dim3(1, 64, BH_), 256>>>(
        64, q, 64, sQ, klm, 64, sLM,
        s1, 256, sS1, 1.f, 0.f, nullptr, nullptr, nullptr, nullptr, nullptr);

    // 4. attn2 = softmax(qlm @ klm^T) — fused
    gemm_tc<64,256,1,8,1,7><<<dim3(1, 4, BH_), 256>>>(
        64, qlm, 64, sLM, klm, 64, sLM,
        a2, 256, sMM, 1.f, 0.f, nullptr, nullptr, nullptr, nullptr, nullptr);

    // 5. sim3 = qlm @ k^T (UNROUNDED store) ; softmax4096 writes rounded
    gemm_tc<128,128,2,4,1,0,1,0><<<dim3(32, 2, BH_), 256>>>(
        64, qlm, 64, sLM, k, 64, sQ,
        s3, 4096, (long long)M_ * N_, 1.f, 0.f, nullptr, nullptr, nullptr, nullptr, nullptr);
    softmax4096<<<BH_ * M_, 256>>>(s3);

    // 6. pinv init
    zero_gmax<<<1, 1>>>(gm);
    pinv_scales<<<BH_, 256>>>(a2, gm);
    pinv_init<<<(BH_ * M_ * M_) / 256, 256>>>(a2, z, gm);

    // 7. Newton-Schulz x6
    float* za = z;
    float* zb = z2;
    for (int it = 0; it < 6; it++) {
        gemm_tc<128,128,2,4,0,3><<<dim3(2, 2, BH_), 256>>>(
            256, a2, 256, sMM, za, 256, sMM,
            xz, 256, sMM, 1.f, 7.f, t1, nullptr, nullptr, nullptr, nullptr);
        gemm_tc<128,128,2,4,0,2><<<dim3(2, 2, BH_), 256>>>(
            256, xz, 256, sMM, t1, 256, sMM,
            t3, 256, sMM, 1.f, 15.f, nullptr, nullptr, nullptr, nullptr, nullptr);
        gemm_tc<128,128,2,4,0,2><<<dim3(2, 2, BH_), 256>>>(
            256, xz, 256, sMM, t3, 256, sMM,
            t5, 256, sMM, 1.f, 13.f, nullptr, nullptr, nullptr, nullptr, nullptr);
        gemm_tc<128,128,2,4,0,0><<<dim3(2, 2, BH_), 256>>>(
            256, za, 256, sMM, t5, 256, sMM,
            zb, 256, sMM, 0.25f, 0.f, nullptr, nullptr, nullptr, nullptr, nullptr);
        float* sw = za; za = zb; zb = sw;
    }

    // 8. a3v = attn3 @ v — split-K x4 (partials unrounded, reduce4 rounds)
    gemm_tc<128,64,4,2,0,0,4,0><<<dim3(1, 2, BH_ * 4), 256>>>(
        1024, s3, 4096, (long long)M_ * N_, v, 64, sQ,
        part, 64, sLM, 1.f, 0.f, nullptr, nullptr, nullptr, nullptr, nullptr);
    reduce4<<<(BH_ * M_ * DH_) / 256, 256>>>(part, a3v);

    // 9. zv = z @ a3v
    gemm_tc<128,64,4,2,0,0><<<dim3(1, 2, BH_), 256>>>(
        256, za, 256, sMM, a3v, 64, sLM,
        zv, 64, sLM, 1.f, 0.f, nullptr, nullptr, nullptr, nullptr, nullptr);

    // 10. out = attn1 @ zv  -> 'of' [b,n,h,d]
    gemm_tc<128,64,4,2,0,6><<<dim3(1, 32, BH_), 256>>>(
        256, s1, 256, sS1, zv, 64, sLM,
        of, 0, 0, 1.f, 0.f, nullptr, nullptr, nullptr, nullptr, nullptr);

    // 11. += depthwise conv of v (rounds result)
    conv_add_of<<<(BH_ * N_ * DH_) / 256, 256>>>(v, rk, of);

    // 12. final projection: y = of @ Wout + bout (not rounded)
    gemm_tc<128,128,2,4,0,4><<<dim3(4, 128, 1), 256>>>(
        512, of, 512, 0, wo, 512, 0,
        yout, 512, 0, 1.f, 0.f, nullptr, bout, nullptr, nullptr, nullptr);
}

// round 7
// speedup vs baseline: 1.3858x; 1.0586x over previous
#include <cuda_runtime.h>
#include <stdint.h>
#include <math.h>

#define B_   4
#define N_   4096
#define DIM_ 512
#define H_   8
#define DH_  64
#define M_   256
#define BH_  32

// ---------------- scratch ----------------------------------------------------
__device__ float g_x  [B_*N_*DIM_];
__device__ float g_wq [DIM_*3*H_*DH_];
__device__ float g_wo [H_*DH_*DIM_];
__device__ float g_q  [BH_*N_*DH_];
__device__ float g_k  [BH_*N_*DH_];
__device__ float g_v  [BH_*N_*DH_];
__device__ float g_qlm[BH_*M_*DH_];
__device__ float g_klm[BH_*M_*DH_];
__device__ float g_s1 [BH_*N_*M_];
__device__ float g_a2 [BH_*M_*M_];
__device__ float g_s3 [BH_*M_*N_];
__device__ float g_z  [BH_*M_*M_];
__device__ float g_z2 [BH_*M_*M_];
__device__ float g_xz [BH_*M_*M_];
__device__ float g_t1 [BH_*M_*M_];
__device__ float g_t3 [BH_*M_*M_];
__device__ float g_t5 [BH_*M_*M_];
__device__ float g_a3v[BH_*M_*DH_];
__device__ float g_zv [BH_*M_*DH_];
__device__ float g_of [B_*N_*DIM_];
__device__ float g_part[4*BH_*M_*DH_];
__device__ float g_gmax[2];

// ---------------- tf32 helpers -----------------------------------------------
__device__ __forceinline__ uint32_t f2tf(float f) {
    uint32_t u; asm("cvt.rna.tf32.f32 %0, %1;" : "=r"(u) : "f"(f)); return u;
}
__device__ __forceinline__ float rtf(float f) { return __uint_as_float(f2tf(f)); }

__device__ __forceinline__ void mma_tf32(float c[4],
    uint32_t a0, uint32_t a1, uint32_t a2, uint32_t a3, uint32_t b0, uint32_t b1)
{
    asm("mma.sync.aligned.m16n8k8.row.col.f32.tf32.tf32.f32 "
        "{%0,%1,%2,%3}, {%4,%5,%6,%7}, {%8,%9}, {%0,%1,%2,%3};"
        : "+f"(c[0]), "+f"(c[1]), "+f"(c[2]), "+f"(c[3])
        : "r"(a0), "r"(a1), "r"(a2), "r"(a3), "r"(b0), "r"(b1));
}

__device__ __forceinline__ void cp16(uint32_t smem, const void* gmem) {
    asm volatile("cp.async.cg.shared.global [%0], [%1], 16;\n"
                 :: "r"(smem), "l"(gmem));
}
__device__ __forceinline__ void cp_commit() {
    asm volatile("cp.async.commit_group;\n" ::: "memory");
}
__device__ __forceinline__ void cp_wait2() {
    asm volatile("cp.async.wait_group 2;\n" ::: "memory");
}

// ---------------- pre-round inputs ---------------------------------------------
__global__ void round_copy(const float* __restrict__ in, float* __restrict__ out)
{
    long long t = (long long)blockIdx.x * 256 + threadIdx.x;
    out[t] = rtf(in[t]);
}

// ---------------- tensor-core batched GEMM (cp.async 4-stage) ------------------
// All MMA-consumed inputs are pre-rounded tf32 — mainloop passes raw bits.
// MODE: 0: alpha*acc   2: dval*I - acc   3: C=acc, C2=dval*I-acc
//       4: acc + bias[col] (not rounded)  5: qkv scatter (q scaled 0.125)
//       6: write [b,n,h,d] 'of' layout    7: fused row softmax (WGM=1)
template<int BM, int BN, int WGM, int WGN, int TRANSB, int MODE, int SPLITK = 1, int RND = 1>
__global__ void __launch_bounds__(256, 2)
gemm_tc(int K,
        const float* __restrict__ A,  int lda, long long sA,
        const float* __restrict__ Bg, int ldb, long long sB,
        float* __restrict__ C, int ldc, long long sC,
        float alpha, float dval,
        float* __restrict__ C2, const float* __restrict__ bias,
        float* __restrict__ oq, float* __restrict__ okk, float* __restrict__ ov)
{
    constexpr int BK = 16;
    constexpr int WM = BM / WGM, WN = BN / WGN;
    constexpr int MI = WM / 16,  NI = WN / 8;
    constexpr int SAW = BK + 4;
    constexpr int SBW = TRANSB ? (BK + 4) : (BN + 8);
    constexpr int ASZ = BM * SAW;
    constexpr int BSZ = TRANSB ? (BN * SAW) : (BK * SBW);
    constexpr int STW = ASZ + BSZ;           // words per stage
    constexpr int A_IT = (BM * 4) / 256;
    constexpr int NB4  = BN / 4;
    constexpr int B0_IT = (BK * NB4) / 256;
    constexpr int B0_KS = 256 / NB4;
    constexpr int B1_IT = (BN * 4) / 256;

    extern __shared__ __align__(16) float dyn[];
    float* red = dyn + 4 * STW;              // MODE 7 only

    const int bz = blockIdx.z;
    const int bh = bz / SPLITK, ks = bz % SPLITK;
    A  += (long long)bh * sA + (long long)ks * K;
    Bg += (long long)bh * sB + (TRANSB ? (long long)ks * K
                                       : (long long)ks * K * ldb);
    if (MODE != 5 && MODE != 6) C += (long long)bz * sC;
    if (MODE == 3) C2 += (long long)bz * sC;

    const int tid = threadIdx.x;
    const int rowBase = blockIdx.y * BM;
    const int colBase = blockIdx.x * BN;
    const int w = tid >> 5, lane = tid & 31;
    const int wm = w / WGN, wn = w % WGN;
    const int tm = lane >> 2, lq = lane & 3;

    float acc[MI][NI][4];
#pragma unroll
    for (int mi = 0; mi < MI; mi++)
#pragma unroll
        for (int ni = 0; ni < NI; ni++)
#pragma unroll
            for (int r = 0; r < 4; r++) acc[mi][ni][r] = 0.f;

    const int ar = tid >> 2, ac = (tid & 3) * 4;
    const int b0k = tid / NB4, b0n = (tid % NB4) * 4;
    const int b1r = tid >> 2, b1c = (tid & 3) * 4;

    const uint32_t dynb = (uint32_t)__cvta_generic_to_shared(dyn);

    auto LOAD = [&](int kt, int buf) {   // body only, no commit
        uint32_t sa = dynb + buf * (STW * 4);
        uint32_t sb = sa + ASZ * 4;
#pragma unroll
        for (int i = 0; i < A_IT; i++) {
            int r = ar + 64 * i;
            cp16(sa + (r * SAW + ac) * 4,
                 A + (long long)(rowBase + r) * lda + kt + ac);
        }
        if (TRANSB == 0) {
#pragma unroll
            for (int i = 0; i < B0_IT; i++) {
                int k = b0k + B0_KS * i;
                cp16(sb + (k * SBW + b0n) * 4,
                     Bg + (long long)(kt + k) * ldb + colBase + b0n);
            }
        } else {
#pragma unroll
            for (int i = 0; i < B1_IT; i++) {
                int r = b1r + 64 * i;
                cp16(sb + (r * SAW + b1c) * 4,
                     Bg + (long long)(colBase + r) * ldb + kt + b1c);
            }
        }
    };

    const int T = K / BK;   // all uses have T >= 4
    // prologue: 3 stages in flight, one commit group each
    LOAD(0, 0); cp_commit();
    LOAD(BK, 1); cp_commit();
    LOAD(2 * BK, 2); cp_commit();

    for (int t = 0; t < T; t++) {
        cp_wait2();                 // group t complete (<=2 newer pending)
        __syncthreads();
        // prefetch into buffer (t+3)&3 == (t-1)&3 — safe after the sync
        if (t + 3 < T) LOAD((t + 3) * BK, (t + 3) & 3);
        cp_commit();                // exactly one group per iteration

        const float* As = dyn + (t & 3) * STW;
        const float* Bs = As + ASZ;
#pragma unroll
        for (int kk = 0; kk < BK; kk += 8) {
            const int kq = kk + lq;
            uint32_t af[MI][4], bf[NI][2];
#pragma unroll
            for (int mi = 0; mi < MI; mi++) {
                int m = wm * WM + mi * 16 + tm;
                af[mi][0] = __float_as_uint(As[ m      * SAW + kq]);
                af[mi][1] = __float_as_uint(As[(m + 8) * SAW + kq]);
                af[mi][2] = __float_as_uint(As[ m      * SAW + kq + 4]);
                af[mi][3] = __float_as_uint(As[(m + 8) * SAW + kq + 4]);
            }
#pragma unroll
            for (int ni = 0; ni < NI; ni++) {
                int n = wn * WN + ni * 8 + tm;
                if (TRANSB == 0) {
                    bf[ni][0] = __float_as_uint(Bs[ kq      * SBW + n]);
                    bf[ni][1] = __float_as_uint(Bs[(kq + 4) * SBW + n]);
                } else {
                    bf[ni][0] = __float_as_uint(Bs[n * SAW + kq]);
                    bf[ni][1] = __float_as_uint(Bs[n * SAW + kq + 4]);
                }
            }
#pragma unroll
            for (int mi = 0; mi < MI; mi++)
#pragma unroll
                for (int ni = 0; ni < NI; ni++)
                    mma_tf32(acc[mi][ni], af[mi][0], af[mi][1], af[mi][2], af[mi][3],
                             bf[ni][0], bf[ni][1]);
        }
        __syncthreads();
    }

    // -------- epilogue --------
    if (MODE == 7) {
        float rmax[MI][2], rsum[MI][2];
#pragma unroll
        for (int mi = 0; mi < MI; mi++)
#pragma unroll
            for (int half = 0; half < 2; half++) {
                float m = -3.4e38f;
#pragma unroll
                for (int ni = 0; ni < NI; ni++)
                    m = fmaxf(m, fmaxf(acc[mi][ni][2 * half], acc[mi][ni][2 * half + 1]));
                m = fmaxf(m, __shfl_xor_sync(~0u, m, 1));
                m = fmaxf(m, __shfl_xor_sync(~0u, m, 2));
                rmax[mi][half] = m;
            }
        if (lq == 0) {
#pragma unroll
            for (int mi = 0; mi < MI; mi++)
#pragma unroll
                for (int half = 0; half < 2; half++)
                    red[(mi * 16 + tm + 8 * half) * WGN + w] = rmax[mi][half];
        }
        __syncthreads();
#pragma unroll
        for (int mi = 0; mi < MI; mi++)
#pragma unroll
            for (int half = 0; half < 2; half++) {
                float m = -3.4e38f;
#pragma unroll
                for (int ww = 0; ww < WGN; ww++)
                    m = fmaxf(m, red[(mi * 16 + tm + 8 * half) * WGN + ww]);
                rmax[mi][half] = m;
            }
        __syncthreads();
#pragma unroll
        for (int mi = 0; mi < MI; mi++)
#pragma unroll
            for (int half = 0; half < 2; half++) {
                float s = 0.f;
#pragma unroll
                for (int ni = 0; ni < NI; ni++) {
                    float e0 = __expf(acc[mi][ni][2 * half]     - rmax[mi][half]);
                    float e1 = __expf(acc[mi][ni][2 * half + 1] - rmax[mi][half]);
                    acc[mi][ni][2 * half]     = e0;
                    acc[mi][ni][2 * half + 1] = e1;
                    s += e0 + e1;
                }
                s += __shfl_xor_sync(~0u, s, 1);
                s += __shfl_xor_sync(~0u, s, 2);
                rsum[mi][half] = s;
            }
        if (lq == 0) {
#pragma unroll
            for (int mi = 0; mi < MI; mi++)
#pragma unroll
                for (int half = 0; half < 2; half++)
                    red[(mi * 16 + tm + 8 * half) * WGN + w] = rsum[mi][half];
        }
        __syncthreads();
#pragma unroll
        for (int mi = 0; mi < MI; mi++)
#pragma unroll
            for (int half = 0; half < 2; half++) {
                float s = 0.f;
#pragma unroll
                for (int ww = 0; ww < WGN; ww++)
                    s += red[(mi * 16 + tm + 8 * half) * WGN + ww];
                rsum[mi][half] = 1.f / s;
            }
#pragma unroll
        for (int mi = 0; mi < MI; mi++) {
#pragma unroll
            for (int ni = 0; ni < NI; ni++) {
                int c = colBase + wn * WN + ni * 8 + 2 * lq;
#pragma unroll
                for (int half = 0; half < 2; half++) {
                    int r = rowBase + mi * 16 + tm + 8 * half;
                    float2 v = make_float2(rtf(acc[mi][ni][2 * half] * rsum[mi][half]),
                                           rtf(acc[mi][ni][2 * half + 1] * rsum[mi][half]));
                    *(float2*)&C[(long long)r * ldc + c] = v;
                }
            }
        }
        return;
    }

#pragma unroll
    for (int mi = 0; mi < MI; mi++) {
        int rBase = rowBase + wm * WM + mi * 16 + tm;
#pragma unroll
        for (int ni = 0; ni < NI; ni++) {
            int c = colBase + wn * WN + ni * 8 + 2 * lq;
#pragma unroll
            for (int half = 0; half < 2; half++) {
                int r = rBase + 8 * half;
                float2 v = make_float2(acc[mi][ni][2 * half], acc[mi][ni][2 * half + 1]);
                if (MODE == 0) {
                    v.x *= alpha; v.y *= alpha;
                    if (RND) { v.x = rtf(v.x); v.y = rtf(v.y); }
                    *(float2*)&C[(long long)r * ldc + c] = v;
                } else if (MODE == 2) {
                    v.x = (r == c     ? dval : 0.f) - v.x;
                    v.y = (r == c + 1 ? dval : 0.f) - v.y;
                    if (RND) { v.x = rtf(v.x); v.y = rtf(v.y); }
                    *(float2*)&C[(long long)r * ldc + c] = v;
                } else if (MODE == 3) {
                    float2 v1 = v;
                    if (RND) { v1.x = rtf(v1.x); v1.y = rtf(v1.y); }
                    *(float2*)&C[(long long)r * ldc + c] = v1;
                    float2 v2;
                    v2.x = (r == c     ? dval : 0.f) - v.x;
                    v2.y = (r == c + 1 ? dval : 0.f) - v.y;
                    if (RND) { v2.x = rtf(v2.x); v2.y = rtf(v2.y); }
                    *(float2*)&C2[(long long)r * ldc + c] = v2;
                } else if (MODE == 4) {
                    v.x += bias[c]; v.y += bias[c + 1];
                    *(float2*)&C[(long long)r * ldc + c] = v;
                } else if (MODE == 5) {
                    int b = r >> 12, n = r & 4095;
                    int part = c >> 9, h = (c >> 6) & 7, d = c & 63;
                    if (part == 0) { v.x *= 0.125f; v.y *= 0.125f; }
                    v.x = rtf(v.x); v.y = rtf(v.y);
                    float* dst = (part == 0) ? oq : ((part == 1) ? okk : ov);
                    *(float2*)&dst[((((long long)(b * 8 + h)) << 12) + n) * 64 + d] = v;
                } else { // 6
                    int b = bz >> 3, h = bz & 7;
                    v.x = rtf(v.x); v.y = rtf(v.y);
                    *(float2*)&C[((long long)(b * 4096 + r)) * 512 + h * 64 + c] = v;
                }
            }
        }
    }
}

// host-side mirror of the dynamic smem requirement
static inline int smem_bytes(int BM, int BN, int TRANSB, int MODE, int WGN) {
    int ASZ = BM * 20;
    int BSZ = TRANSB ? BN * 20 : 16 * (BN + 8);
    int b = 4 * (ASZ + BSZ) * 4;
    if (MODE == 7) b += BM * WGN * 4;
    return b;
}

// ---------------- split-K reduction (4 partials) --------------------------------
__global__ void reduce4(const float* __restrict__ p, float* __restrict__ out)
{
    long long t = (long long)blockIdx.x * 256 + threadIdx.x;
    int bh = (int)(t >> 14);
    int e  = (int)(t & 16383);
    const float* pp = p + ((long long)bh * 4) * 16384 + e;
    out[t] = rtf(pp[0] + pp[16384] + pp[2 * 16384] + pp[3 * 16384]);
}

// ---------------- landmarks ---------------------------------------------------
__global__ void landmarks_kernel(const float* __restrict__ q, const float* __restrict__ k,
                                 float* __restrict__ qlm, float* __restrict__ klm)
{
    int idx = blockIdx.x;
    int d = threadIdx.x;
    long long base = ((long long)idx * 16) * 64 + d;
    float sq = 0.f, sk = 0.f;
#pragma unroll
    for (int j = 0; j < 16; j++) {
        sq += q[base + j * 64];
        sk += k[base + j * 64];
    }
    qlm[(long long)idx * 64 + d] = rtf(sq * 0.0625f);
    klm[(long long)idx * 64 + d] = rtf(sk * 0.0625f);
}

// ---------------- softmax for 4096-wide rows ------------------------------------
__global__ void softmax4096(float* __restrict__ data)
{
    __shared__ float redm[8], reds[8];
    float4* p = (float4*)(data + ((long long)blockIdx.x << 12));
    int tid = threadIdx.x;
    float4 v[4];
#pragma unroll
    for (int i = 0; i < 4; i++) v[i] = p[tid + 256 * i];
    float m = -3.4e38f;
#pragma unroll
    for (int i = 0; i < 4; i++)
        m = fmaxf(m, fmaxf(fmaxf(v[i].x, v[i].y), fmaxf(v[i].z, v[i].w)));
#pragma unroll
    for (int s = 16; s; s >>= 1) m = fmaxf(m, __shfl_xor_sync(~0u, m, s));
    if ((tid & 31) == 0) redm[tid >> 5] = m;
    __syncthreads();
#pragma unroll
    for (int j = 0; j < 8; j++) m = fmaxf(m, redm[j]);

    float sum = 0.f;
#pragma unroll
    for (int i = 0; i < 4; i++) {
        v[i].x = __expf(v[i].x - m); v[i].y = __expf(v[i].y - m);
        v[i].z = __expf(v[i].z - m); v[i].w = __expf(v[i].w - m);
        sum += v[i].x + v[i].y + v[i].z + v[i].w;
    }
#pragma unroll
    for (int s = 16; s; s >>= 1) sum += __shfl_xor_sync(~0u, sum, s);
    if ((tid & 31) == 0) reds[tid >> 5] = sum;
    __syncthreads();
    sum = 0.f;
#pragma unroll
    for (int j = 0; j < 8; j++) sum += reds[j];
    float inv = 1.f / sum;
#pragma unroll
    for (int i = 0; i < 4; i++) {
        v[i].x = rtf(v[i].x * inv); v[i].y = rtf(v[i].y * inv);
        v[i].z = rtf(v[i].z * inv); v[i].w = rtf(v[i].w * inv);
        p[tid + 256 * i] = v[i];
    }
}

// ---------------- pinv init ----------------------------------------------------
__global__ void zero_gmax(float* gm) { gm[0] = 0.f; gm[1] = 0.f; }

__global__ void pinv_scales(const float* __restrict__ a, float* gm)
{
    __shared__ float red[256];
    int bh = blockIdx.x, tid = threadIdx.x;
    const float* A = a + ((long long)bh << 16);
    float rs = 0.f;
    for (int j = 0; j < 256; j++) rs += fabsf(A[tid * 256 + j]);
    red[tid] = rs; __syncthreads();
    for (int s = 128; s > 0; s >>= 1) {
        if (tid < s) red[tid] = fmaxf(red[tid], red[tid + s]);
        __syncthreads();
    }
    if (tid == 0) atomicMax((int*)&gm[0], __float_as_int(red[0]));
    __syncthreads();
    float cs = 0.f;
    for (int i = 0; i < 256; i++) cs += fabsf(A[i * 256 + tid]);
    red[tid] = cs; __syncthreads();
    for (int s = 128; s > 0; s >>= 1) {
        if (tid < s) red[tid] = fmaxf(red[tid], red[tid + s]);
        __syncthreads();
    }
    if (tid == 0) atomicMax((int*)&gm[1], __float_as_int(red[0]));
}

__global__ void pinv_init(const float* __restrict__ a, float* __restrict__ z,
                          const float* __restrict__ gm)
{
    long long t = (long long)blockIdx.x * 256 + threadIdx.x;
    int bh = (int)(t >> 16);
    int ij = (int)(t & 65535);
    int i = ij >> 8, j = ij & 255;
    float inv = 1.f / (gm[0] * gm[1]);
    z[((long long)bh << 16) + ij] = rtf(a[((long long)bh << 16) + (j << 8) + i] * inv);
}

// ---------------- depthwise conv, accumulates into 'of' layout ------------------
__global__ void conv_add_of(const float* __restrict__ v, const float* __restrict__ w,
                            float* __restrict__ of)
{
    long long t = (long long)blockIdx.x * 256 + threadIdx.x;
    int d = (int)(t & 63);
    long long r = t >> 6;
    int n  = (int)(r & 4095);
    int bh = (int)(r >> 12);
    int h  = bh & 7, b = bh >> 3;
    const float* vp = v + ((long long)bh << 18) + d;
    float s = 0.f;
#pragma unroll
    for (int tp = 0; tp < 33; tp++) {
        int nn = n + tp - 16;
        if (nn >= 0 && nn < 4096)
            s = fmaf(vp[(long long)nn << 6], w[h * 33 + tp], s);
    }
    long long oidx = ((long long)(b * 4096 + n)) * 512 + h * 64 + d;
    of[oidx] = rtf(of[oidx] + s);
}

// ---------------- host orchestration -------------------------------------------
extern "C" void kernel_launch(void* const* d_in, const int* in_sizes, int n_in,
                              void* d_out, int out_size)
{
    const float* x    = (const float*)d_in[0];
    const float* Wqkv = (const float*)d_in[1];
    const float* Wout = (const float*)d_in[2];
    const float* bout = (const float*)d_in[3];
    const float* rk   = (const float*)d_in[4];
    float* yout = (float*)d_out;

    float *xr, *wq, *wo, *q, *k, *v, *qlm, *klm, *s1, *a2, *s3, *z, *z2, *xz,
          *t1, *t3, *t5, *a3v, *zv, *of, *part, *gm;
    cudaGetSymbolAddress((void**)&xr,  g_x);
    cudaGetSymbolAddress((void**)&wq,  g_wq);
    cudaGetSymbolAddress((void**)&wo,  g_wo);
    cudaGetSymbolAddress((void**)&q,   g_q);
    cudaGetSymbolAddress((void**)&k,   g_k);
    cudaGetSymbolAddress((void**)&v,   g_v);
    cudaGetSymbolAddress((void**)&qlm, g_qlm);
    cudaGetSymbolAddress((void**)&klm, g_klm);
    cudaGetSymbolAddress((void**)&s1,  g_s1);
    cudaGetSymbolAddress((void**)&a2,  g_a2);
    cudaGetSymbolAddress((void**)&s3,  g_s3);
    cudaGetSymbolAddress((void**)&z,   g_z);
    cudaGetSymbolAddress((void**)&z2,  g_z2);
    cudaGetSymbolAddress((void**)&xz,  g_xz);
    cudaGetSymbolAddress((void**)&t1,  g_t1);
    cudaGetSymbolAddress((void**)&t3,  g_t3);
    cudaGetSymbolAddress((void**)&t5,  g_t5);
    cudaGetSymbolAddress((void**)&a3v, g_a3v);
    cudaGetSymbolAddress((void**)&zv,  g_zv);
    cudaGetSymbolAddress((void**)&of,  g_of);
    cudaGetSymbolAddress((void**)&part,g_part);
    cudaGetSymbolAddress((void**)&gm,  g_gmax);

    const long long sQ  = (long long)N_ * DH_;
    const long long sLM = (long long)M_ * DH_;
    const long long sS1 = (long long)N_ * M_;
    const long long sMM = (long long)M_ * M_;

    // one-time dynamic smem caps (idempotent)
    static bool attr_done = false;
    if (!attr_done) {
        cudaFuncSetAttribute(gemm_tc<128,128,2,4,0,5>, cudaFuncAttributeMaxDynamicSharedMemorySize, smem_bytes(128,128,0,5,4));
        cudaFuncSetAttribute(gemm_tc<64,256,1,8,1,7>,  cudaFuncAttributeMaxDynamicSharedMemorySize, smem_bytes(64,256,1,7,8));
        cudaFuncSetAttribute(gemm_tc<128,128,2,4,1,0,1,0>, cudaFuncAttributeMaxDynamicSharedMemorySize, smem_bytes(128,128,1,0,4));
        cudaFuncSetAttribute(gemm_tc<128,128,2,4,0,3>, cudaFuncAttributeMaxDynamicSharedMemorySize, smem_bytes(128,128,0,3,4));
        cudaFuncSetAttribute(gemm_tc<128,128,2,4,0,2>, cudaFuncAttributeMaxDynamicSharedMemorySize, smem_bytes(128,128,0,2,4));
        cudaFuncSetAttribute(gemm_tc<128,128,2,4,0,0>, cudaFuncAttributeMaxDynamicSharedMemorySize, smem_bytes(128,128,0,0,4));
        cudaFuncSetAttribute(gemm_tc<128,64,4,2,0,0,4,0>, cudaFuncAttributeMaxDynamicSharedMemorySize, smem_bytes(128,64,0,0,2));
        cudaFuncSetAttribute(gemm_tc<128,64,4,2,0,0>, cudaFuncAttributeMaxDynamicSharedMemorySize, smem_bytes(128,64,0,0,2));
        cudaFuncSetAttribute(gemm_tc<128,64,4,2,0,6>, cudaFuncAttributeMaxDynamicSharedMemorySize, smem_bytes(128,64,0,6,2));
        cudaFuncSetAttribute(gemm_tc<128,128,2,4,0,4>, cudaFuncAttributeMaxDynamicSharedMemorySize, smem_bytes(128,128,0,4,4));
        attr_done = true;
    }

    // 0. pre-round harness inputs to tf32
    round_copy<<<(B_*N_*DIM_) / 256, 256>>>(x, xr);
    round_copy<<<(DIM_*3*H_*DH_) / 256, 256>>>(Wqkv, wq);
    round_copy<<<(H_*DH_*DIM_) / 256, 256>>>(Wout, wo);

    // 1. qkv projection with scatter
    gemm_tc<128,128,2,4,0,5><<<dim3(12, 128, 1), 256, smem_bytes(128,128,0,5,4)>>>(
        512, xr, 512, 0, wq, 1536, 0,
        nullptr, 0, 0, 1.f, 0.f, nullptr, nullptr, q, k, v);

    // 2. landmarks
    landmarks_kernel<<<BH_ * M_, DH_>>>(q, k, qlm, klm);

    // 3. attn1 = softmax(q @ klm^T)
    gemm_tc<64,256,1,8,1,7><<<dim3(1, 64, BH_), 256, smem_bytes(64,256,1,7,8)>>>(
        64, q, 64, sQ, klm, 64, sLM,
        s1, 256, sS1, 1.f, 0.f, nullptr, nullptr, nullptr, nullptr, nullptr);

    // 4. attn2 = softmax(qlm @ klm^T)
    gemm_tc<64,256,1,8,1,7><<<dim3(1, 4, BH_), 256, smem_bytes(64,256,1,7,8)>>>(
        64, qlm, 64, sLM, klm, 64, sLM,
        a2, 256, sMM, 1.f, 0.f, nullptr, nullptr, nullptr, nullptr, nullptr);

    // 5. sim3 = qlm @ k^T (unrounded) ; softmax4096 rounds
    gemm_tc<128,128,2,4,1,0,1,0><<<dim3(32, 2, BH_), 256, smem_bytes(128,128,1,0,4)>>>(
        64, qlm, 64, sLM, k, 64, sQ,
        s3, 4096, (long long)M_ * N_, 1.f, 0.f, nullptr, nullptr, nullptr, nullptr, nullptr);
    softmax4096<<<BH_ * M_, 256>>>(s3);

    // 6. pinv init
    zero_gmax<<<1, 1>>>(gm);
    pinv_scales<<<BH_, 256>>>(a2, gm);
    pinv_init<<<(BH_ * M_ * M_) / 256, 256>>>(a2, z, gm);

    // 7. Newton-Schulz x6
    float* za = z;
    float* zb = z2;
    for (int it = 0; it < 6; it++) {
        gemm_tc<128,128,2,4,0,3><<<dim3(2, 2, BH_), 256, smem_bytes(128,128,0,3,4)>>>(
            256, a2, 256, sMM, za, 256, sMM,
            xz, 256, sMM, 1.f, 7.f, t1, nullptr, nullptr, nullptr, nullptr);
        gemm_tc<128,128,2,4,0,2><<<dim3(2, 2, BH_), 256, smem_bytes(128,128,0,2,4)>>>(
            256, xz, 256, sMM, t1, 256, sMM,
            t3, 256, sMM, 1.f, 15.f, nullptr, nullptr, nullptr, nullptr, nullptr);
        gemm_tc<128,128,2,4,0,2><<<dim3(2, 2, BH_), 256, smem_bytes(128,128,0,2,4)>>>(
            256, xz, 256, sMM, t3, 256, sMM,
            t5, 256, sMM, 1.f, 13.f, nullptr, nullptr, nullptr, nullptr, nullptr);
        gemm_tc<128,128,2,4,0,0><<<dim3(2, 2, BH_), 256, smem_bytes(128,128,0,0,4)>>>(
            256, za, 256, sMM, t5, 256, sMM,
            zb, 256, sMM, 0.25f, 0.f, nullptr, nullptr, nullptr, nullptr, nullptr);
        float* sw = za; za = zb; zb = sw;
    }

    // 8. a3v = attn3 @ v — split-K x4
    gemm_tc<128,64,4,2,0,0,4,0><<<dim3(1, 2, BH_ * 4), 256, smem_bytes(128,64,0,0,2)>>>(
        1024, s3, 4096, (long long)M_ * N_, v, 64, sQ,
        part, 64, sLM, 1.f, 0.f, nullptr, nullptr, nullptr, nullptr, nullptr);
    reduce4<<<(BH_ * M_ * DH_) / 256, 256>>>(part, a3v);

    // 9. zv = z @ a3v
    gemm_tc<128,64,4,2,0,0><<<dim3(1, 2, BH_), 256, smem_bytes(128,64,0,0,2)>>>(
        256, za, 256, sMM, a3v, 64, sLM,
        zv, 64, sLM, 1.f, 0.f, nullptr, nullptr, nullptr, nullptr, nullptr);

    // 10. out = attn1 @ zv -> 'of'
    gemm_tc<128,64,4,2,0,6><<<dim3(1, 32, BH_), 256, smem_bytes(128,64,0,6,2)>>>(
        256, s1, 256, sS1, zv, 64, sLM,
        of, 0, 0, 1.f, 0.f, nullptr, nullptr, nullptr, nullptr, nullptr);

    // 11. += depthwise conv of v
    conv_add_of<<<(BH_ * N_ * DH_) / 256, 256>>>(v, rk, of);

    // 12. final projection
    gemm_tc<128,128,2,4,0,4><<<dim3(4, 128, 1), 256, smem_bytes(128,128,0,4,4)>>>(
        512, of, 512, 0, wo, 512, 0,
        yout, 512, 0, 1.f, 0.f, nullptr, bout, nullptr, nullptr, nullptr);
}

// round 8
// speedup vs baseline: 1.4956x; 1.0792x over previous
#include <cuda_runtime.h>
#include <stdint.h>
#include <math.h>

#define B_   4
#define N_   4096
#define DIM_ 512
#define H_   8
#define DH_  64
#define M_   256
#define BH_  32

// ---------------- scratch ----------------------------------------------------
__device__ float g_x  [B_*N_*DIM_];
__device__ float g_wq [DIM_*3*H_*DH_];
__device__ float g_wo [H_*DH_*DIM_];
__device__ float g_q  [BH_*N_*DH_];
__device__ float g_k  [BH_*N_*DH_];
__device__ float g_v  [BH_*N_*DH_];
__device__ float g_qlm[BH_*M_*DH_];
__device__ float g_klm[BH_*M_*DH_];
__device__ float g_s1 [BH_*N_*M_];
__device__ float g_a2 [BH_*M_*M_];
__device__ float g_s3 [BH_*M_*N_];
__device__ float g_z  [BH_*M_*M_];
__device__ float g_z2 [BH_*M_*M_];
__device__ float g_xz [BH_*M_*M_];
__device__ float g_t1 [BH_*M_*M_];
__device__ float g_t3 [BH_*M_*M_];
__device__ float g_t5 [BH_*M_*M_];
__device__ float g_a3v[BH_*M_*DH_];
__device__ float g_zv [BH_*M_*DH_];
__device__ float g_of [B_*N_*DIM_];
__device__ float g_part[4*BH_*M_*DH_];
__device__ float g_gmax[2];

// ---------------- tf32 helpers -----------------------------------------------
__device__ __forceinline__ uint32_t f2tf(float f) {
    uint32_t u; asm("cvt.rna.tf32.f32 %0, %1;" : "=r"(u) : "f"(f)); return u;
}
__device__ __forceinline__ float rtf(float f) { return __uint_as_float(f2tf(f)); }

__device__ __forceinline__ void mma_tf32(float c[4],
    uint32_t a0, uint32_t a1, uint32_t a2, uint32_t a3, uint32_t b0, uint32_t b1)
{
    asm("mma.sync.aligned.m16n8k8.row.col.f32.tf32.tf32.f32 "
        "{%0,%1,%2,%3}, {%4,%5,%6,%7}, {%8,%9}, {%0,%1,%2,%3};"
        : "+f"(c[0]), "+f"(c[1]), "+f"(c[2]), "+f"(c[3])
        : "r"(a0), "r"(a1), "r"(a2), "r"(a3), "r"(b0), "r"(b1));
}

__device__ __forceinline__ void cp16(uint32_t smem, const void* gmem) {
    asm volatile("cp.async.cg.shared.global [%0], [%1], 16;\n"
                 :: "r"(smem), "l"(gmem));
}
__device__ __forceinline__ void cp_commit() {
    asm volatile("cp.async.commit_group;\n" ::: "memory");
}
template<int N>
__device__ __forceinline__ void cp_waitg() {
    asm volatile("cp.async.wait_group %0;\n" :: "n"(N) : "memory");
}

// ---------------- pre-round inputs ---------------------------------------------
__global__ void round_copy(const float* __restrict__ in, float* __restrict__ out)
{
    long long t = (long long)blockIdx.x * 256 + threadIdx.x;
    out[t] = rtf(in[t]);
}

// ---------------- tensor-core batched GEMM (cp.async multi-stage, frag ILP) ----
// MODE: 0: alpha*acc   2: dval*I - acc   3: C=acc, C2=dval*I-acc
//       4: acc + bias[col] (not rounded)  5: qkv scatter (q scaled 0.125)
//       6: write [b,n,h,d] 'of' layout    7: fused row softmax (WGM=1)
template<int BM, int BN, int WGM, int WGN, int TRANSB, int MODE,
         int BK = 16, int STAGES = 4, int SPLITK = 1, int RND = 1>
__global__ void __launch_bounds__(256, 2)
gemm_tc(int K,
        const float* __restrict__ A,  int lda, long long sA,
        const float* __restrict__ Bg, int ldb, long long sB,
        float* __restrict__ C, int ldc, long long sC,
        float alpha, float dval,
        float* __restrict__ C2, const float* __restrict__ bias,
        float* __restrict__ oq, float* __restrict__ okk, float* __restrict__ ov)
{
    constexpr int WM = BM / WGM, WN = BN / WGN;
    constexpr int MI = WM / 16,  NI = WN / 8;
    constexpr int NSTEP = BK / 8;
    constexpr int SAW = BK + 4;
    constexpr int SBW = TRANSB ? (BK + 4) : (BN + 8);
    constexpr int ASZ = BM * SAW;
    constexpr int BSZ = TRANSB ? (BN * SAW) : (BK * SBW);
    constexpr int STW = ASZ + BSZ;
    constexpr int CPR = BK / 4;          // 16B chunks per k-row
    constexpr int RPI = 256 / CPR;       // rows covered per cp iteration
    constexpr int A_IT  = BM / RPI;
    constexpr int B1_IT = BN / RPI;
    constexpr int NB4   = BN / 4;
    constexpr int B0_RS = 256 / NB4;
    constexpr int B0_IT = BK / B0_RS;

    extern __shared__ __align__(16) float dyn[];
    float* red = dyn + STAGES * STW;     // MODE 7 only

    const int bz = blockIdx.z;
    const int bh = bz / SPLITK, ks = bz % SPLITK;
    A  += (long long)bh * sA + (long long)ks * K;
    Bg += (long long)bh * sB + (TRANSB ? (long long)ks * K
                                       : (long long)ks * K * ldb);
    if (MODE != 5 && MODE != 6) C += (long long)bz * sC;
    if (MODE == 3) C2 += (long long)bz * sC;

    const int tid = threadIdx.x;
    const int rowBase = blockIdx.y * BM;
    const int colBase = blockIdx.x * BN;
    const int w = tid >> 5, lane = tid & 31;
    const int wm = w / WGN, wn = w % WGN;
    const int tm = lane >> 2, lq = lane & 3;

    float acc[MI][NI][4];
#pragma unroll
    for (int mi = 0; mi < MI; mi++)
#pragma unroll
        for (int ni = 0; ni < NI; ni++)
#pragma unroll
            for (int r = 0; r < 4; r++) acc[mi][ni][r] = 0.f;

    const int a_r = tid / CPR, a_c = (tid % CPR) * 4;
    const int b0k = tid / NB4, b0n = (tid % NB4) * 4;

    const uint32_t dynb = (uint32_t)__cvta_generic_to_shared(dyn);

    auto LOADG = [&](int kt, int buf) {
        uint32_t sa = dynb + buf * (STW * 4);
        uint32_t sb = sa + ASZ * 4;
#pragma unroll
        for (int i = 0; i < A_IT; i++) {
            int r = a_r + RPI * i;
            cp16(sa + (r * SAW + a_c) * 4,
                 A + (long long)(rowBase + r) * lda + kt + a_c);
        }
        if (TRANSB == 0) {
#pragma unroll
            for (int i = 0; i < B0_IT; i++) {
                int k = b0k + B0_RS * i;
                cp16(sb + (k * SBW + b0n) * 4,
                     Bg + (long long)(kt + k) * ldb + colBase + b0n);
            }
        } else {
#pragma unroll
            for (int i = 0; i < B1_IT; i++) {
                int r = a_r + RPI * i;
                cp16(sb + (r * SAW + a_c) * 4,
                     Bg + (long long)(colBase + r) * ldb + kt + a_c);
            }
        }
    };

    auto LDF = [&](const float* As, const float* Bs, int kk,
                   uint32_t (*af)[4], uint32_t (*bf)[2]) {
        const int kq = kk + lq;
#pragma unroll
        for (int mi = 0; mi < MI; mi++) {
            int m = wm * WM + mi * 16 + tm;
            af[mi][0] = __float_as_uint(As[ m      * SAW + kq]);
            af[mi][1] = __float_as_uint(As[(m + 8) * SAW + kq]);
            af[mi][2] = __float_as_uint(As[ m      * SAW + kq + 4]);
            af[mi][3] = __float_as_uint(As[(m + 8) * SAW + kq + 4]);
        }
#pragma unroll
        for (int ni = 0; ni < NI; ni++) {
            int n = wn * WN + ni * 8 + tm;
            if (TRANSB == 0) {
                bf[ni][0] = __float_as_uint(Bs[ kq      * SBW + n]);
                bf[ni][1] = __float_as_uint(Bs[(kq + 4) * SBW + n]);
            } else {
                bf[ni][0] = __float_as_uint(Bs[n * SAW + kq]);
                bf[ni][1] = __float_as_uint(Bs[n * SAW + kq + 4]);
            }
        }
    };

    auto MMAS = [&](uint32_t (*af)[4], uint32_t (*bf)[2]) {
#pragma unroll
        for (int mi = 0; mi < MI; mi++)
#pragma unroll
            for (int ni = 0; ni < NI; ni++)
                mma_tf32(acc[mi][ni], af[mi][0], af[mi][1], af[mi][2], af[mi][3],
                         bf[ni][0], bf[ni][1]);
    };

    const int T = K / BK;
#pragma unroll
    for (int s = 0; s < STAGES - 1; s++) { LOADG(s * BK, s); cp_commit(); }

    for (int t = 0; t < T; t++) {
        cp_waitg<STAGES - 2>();
        __syncthreads();
        if (t + STAGES - 1 < T) LOADG((t + STAGES - 1) * BK, (t + STAGES - 1) % STAGES);
        cp_commit();

        const float* As = dyn + (t % STAGES) * STW;
        const float* Bs = As + ASZ;

        uint32_t af0[MI][4], bf0[NI][2], af1[MI][4], bf1[NI][2];
        LDF(As, Bs, 0, af0, bf0);
#pragma unroll
        for (int s = 0; s < NSTEP; s++) {
            if (s + 1 < NSTEP) {
                if ((s & 1) == 0) LDF(As, Bs, (s + 1) * 8, af1, bf1);
                else              LDF(As, Bs, (s + 1) * 8, af0, bf0);
            }
            if ((s & 1) == 0) MMAS(af0, bf0);
            else              MMAS(af1, bf1);
        }
        __syncthreads();
    }

    // -------- epilogue --------
    if (MODE == 7) {
        float rmax[MI][2], rsum[MI][2];
#pragma unroll
        for (int mi = 0; mi < MI; mi++)
#pragma unroll
            for (int half = 0; half < 2; half++) {
                float m = -3.4e38f;
#pragma unroll
                for (int ni = 0; ni < NI; ni++)
                    m = fmaxf(m, fmaxf(acc[mi][ni][2 * half], acc[mi][ni][2 * half + 1]));
                m = fmaxf(m, __shfl_xor_sync(~0u, m, 1));
                m = fmaxf(m, __shfl_xor_sync(~0u, m, 2));
                rmax[mi][half] = m;
            }
        if (lq == 0) {
#pragma unroll
            for (int mi = 0; mi < MI; mi++)
#pragma unroll
                for (int half = 0; half < 2; half++)
                    red[(mi * 16 + tm + 8 * half) * WGN + w] = rmax[mi][half];
        }
        __syncthreads();
#pragma unroll
        for (int mi = 0; mi < MI; mi++)
#pragma unroll
            for (int half = 0; half < 2; half++) {
                float m = -3.4e38f;
#pragma unroll
                for (int ww = 0; ww < WGN; ww++)
                    m = fmaxf(m, red[(mi * 16 + tm + 8 * half) * WGN + ww]);
                rmax[mi][half] = m;
            }
        __syncthreads();
#pragma unroll
        for (int mi = 0; mi < MI; mi++)
#pragma unroll
            for (int half = 0; half < 2; half++) {
                float s = 0.f;
#pragma unroll
                for (int ni = 0; ni < NI; ni++) {
                    float e0 = __expf(acc[mi][ni][2 * half]     - rmax[mi][half]);
                    float e1 = __expf(acc[mi][ni][2 * half + 1] - rmax[mi][half]);
                    acc[mi][ni][2 * half]     = e0;
                    acc[mi][ni][2 * half + 1] = e1;
                    s += e0 + e1;
                }
                s += __shfl_xor_sync(~0u, s, 1);
                s += __shfl_xor_sync(~0u, s, 2);
                rsum[mi][half] = s;
            }
        if (lq == 0) {
#pragma unroll
            for (int mi = 0; mi < MI; mi++)
#pragma unroll
                for (int half = 0; half < 2; half++)
                    red[(mi * 16 + tm + 8 * half) * WGN + w] = rsum[mi][half];
        }
        __syncthreads();
#pragma unroll
        for (int mi = 0; mi < MI; mi++)
#pragma unroll
            for (int half = 0; half < 2; half++) {
                float s = 0.f;
#pragma unroll
                for (int ww = 0; ww < WGN; ww++)
                    s += red[(mi * 16 + tm + 8 * half) * WGN + ww];
                rsum[mi][half] = 1.f / s;
            }
#pragma unroll
        for (int mi = 0; mi < MI; mi++) {
#pragma unroll
            for (int ni = 0; ni < NI; ni++) {
                int c = colBase + wn * WN + ni * 8 + 2 * lq;
#pragma unroll
                for (int half = 0; half < 2; half++) {
                    int r = rowBase + mi * 16 + tm + 8 * half;
                    float2 v = make_float2(rtf(acc[mi][ni][2 * half] * rsum[mi][half]),
                                           rtf(acc[mi][ni][2 * half + 1] * rsum[mi][half]));
                    *(float2*)&C[(long long)r * ldc + c] = v;
                }
            }
        }
        return;
    }

#pragma unroll
    for (int mi = 0; mi < MI; mi++) {
        int rBase = rowBase + wm * WM + mi * 16 + tm;
#pragma unroll
        for (int ni = 0; ni < NI; ni++) {
            int c = colBase + wn * WN + ni * 8 + 2 * lq;
#pragma unroll
            for (int half = 0; half < 2; half++) {
                int r = rBase + 8 * half;
                float2 v = make_float2(acc[mi][ni][2 * half], acc[mi][ni][2 * half + 1]);
                if (MODE == 0) {
                    v.x *= alpha; v.y *= alpha;
                    if (RND) { v.x = rtf(v.x); v.y = rtf(v.y); }
                    *(float2*)&C[(long long)r * ldc + c] = v;
                } else if (MODE == 2) {
                    v.x = (r == c     ? dval : 0.f) - v.x;
                    v.y = (r == c + 1 ? dval : 0.f) - v.y;
                    if (RND) { v.x = rtf(v.x); v.y = rtf(v.y); }
                    *(float2*)&C[(long long)r * ldc + c] = v;
                } else if (MODE == 3) {
                    float2 v1 = v;
                    if (RND) { v1.x = rtf(v1.x); v1.y = rtf(v1.y); }
                    *(float2*)&C[(long long)r * ldc + c] = v1;
                    float2 v2;
                    v2.x = (r == c     ? dval : 0.f) - v.x;
                    v2.y = (r == c + 1 ? dval : 0.f) - v.y;
                    if (RND) { v2.x = rtf(v2.x); v2.y = rtf(v2.y); }
                    *(float2*)&C2[(long long)r * ldc + c] = v2;
                } else if (MODE == 4) {
                    v.x += bias[c]; v.y += bias[c + 1];
                    *(float2*)&C[(long long)r * ldc + c] = v;
                } else if (MODE == 5) {
                    int b = r >> 12, n = r & 4095;
                    int part = c >> 9, h = (c >> 6) & 7, d = c & 63;
                    if (part == 0) { v.x *= 0.125f; v.y *= 0.125f; }
                    v.x = rtf(v.x); v.y = rtf(v.y);
                    float* dst = (part == 0) ? oq : ((part == 1) ? okk : ov);
                    *(float2*)&dst[((((long long)(b * 8 + h)) << 12) + n) * 64 + d] = v;
                } else { // 6
                    int b = bz >> 3, h = bz & 7;
                    v.x = rtf(v.x); v.y = rtf(v.y);
                    *(float2*)&C[((long long)(b * 4096 + r)) * 512 + h * 64 + c] = v;
                }
            }
        }
    }
}

// host-side mirror of the dynamic smem requirement
static inline int smem_bytes(int BM, int BN, int TRANSB, int MODE, int WGN,
                             int BK, int STAGES) {
    int ASZ = BM * (BK + 4);
    int BSZ = TRANSB ? BN * (BK + 4) : BK * (BN + 8);
    int b = STAGES * (ASZ + BSZ) * 4;
    if (MODE == 7) b += BM * WGN * 4;
    return b;
}

// ---------------- split-K reduction (4 partials) --------------------------------
__global__ void reduce4(const float* __restrict__ p, float* __restrict__ out)
{
    long long t = (long long)blockIdx.x * 256 + threadIdx.x;
    int bh = (int)(t >> 14);
    int e  = (int)(t & 16383);
    const float* pp = p + ((long long)bh * 4) * 16384 + e;
    out[t] = rtf(pp[0] + pp[16384] + pp[2 * 16384] + pp[3 * 16384]);
}

// ---------------- landmarks ---------------------------------------------------
__global__ void landmarks_kernel(const float* __restrict__ q, const float* __restrict__ k,
                                 float* __restrict__ qlm, float* __restrict__ klm)
{
    int idx = blockIdx.x;
    int d = threadIdx.x;
    long long base = ((long long)idx * 16) * 64 + d;
    float sq = 0.f, sk = 0.f;
#pragma unroll
    for (int j = 0; j < 16; j++) {
        sq += q[base + j * 64];
        sk += k[base + j * 64];
    }
    qlm[(long long)idx * 64 + d] = rtf(sq * 0.0625f);
    klm[(long long)idx * 64 + d] = rtf(sk * 0.0625f);
}

// ---------------- softmax for 4096-wide rows ------------------------------------
__global__ void softmax4096(float* __restrict__ data)
{
    __shared__ float redm[8], reds[8];
    float4* p = (float4*)(data + ((long long)blockIdx.x << 12));
    int tid = threadIdx.x;
    float4 v[4];
#pragma unroll
    for (int i = 0; i < 4; i++) v[i] = p[tid + 256 * i];
    float m = -3.4e38f;
#pragma unroll
    for (int i = 0; i < 4; i++)
        m = fmaxf(m, fmaxf(fmaxf(v[i].x, v[i].y), fmaxf(v[i].z, v[i].w)));
#pragma unroll
    for (int s = 16; s; s >>= 1) m = fmaxf(m, __shfl_xor_sync(~0u, m, s));
    if ((tid & 31) == 0) redm[tid >> 5] = m;
    __syncthreads();
#pragma unroll
    for (int j = 0; j < 8; j++) m = fmaxf(m, redm[j]);

    float sum = 0.f;
#pragma unroll
    for (int i = 0; i < 4; i++) {
        v[i].x = __expf(v[i].x - m); v[i].y = __expf(v[i].y - m);
        v[i].z = __expf(v[i].z - m); v[i].w = __expf(v[i].w - m);
        sum += v[i].x + v[i].y + v[i].z + v[i].w;
    }
#pragma unroll
    for (int s = 16; s; s >>= 1) sum += __shfl_xor_sync(~0u, sum, s);
    if ((tid & 31) == 0) reds[tid >> 5] = sum;
    __syncthreads();
    sum = 0.f;
#pragma unroll
    for (int j = 0; j < 8; j++) sum += reds[j];
    float inv = 1.f / sum;
#pragma unroll
    for (int i = 0; i < 4; i++) {
        v[i].x = rtf(v[i].x * inv); v[i].y = rtf(v[i].y * inv);
        v[i].z = rtf(v[i].z * inv); v[i].w = rtf(v[i].w * inv);
        p[tid + 256 * i] = v[i];
    }
}

// ---------------- pinv init ----------------------------------------------------
__global__ void zero_gmax(float* gm) { gm[0] = 0.f; gm[1] = 0.f; }

__global__ void pinv_scales(const float* __restrict__ a, float* gm)
{
    __shared__ float red[256];
    int bh = blockIdx.x, tid = threadIdx.x;
    const float* A = a + ((long long)bh << 16);
    float rs = 0.f;
    for (int j = 0; j < 256; j++) rs += fabsf(A[tid * 256 + j]);
    red[tid] = rs; __syncthreads();
    for (int s = 128; s > 0; s >>= 1) {
        if (tid < s) red[tid] = fmaxf(red[tid], red[tid + s]);
        __syncthreads();
    }
    if (tid == 0) atomicMax((int*)&gm[0], __float_as_int(red[0]));
    __syncthreads();
    float cs = 0.f;
    for (int i = 0; i < 256; i++) cs += fabsf(A[i * 256 + tid]);
    red[tid] = cs; __syncthreads();
    for (int s = 128; s > 0; s >>= 1) {
        if (tid < s) red[tid] = fmaxf(red[tid], red[tid + s]);
        __syncthreads();
    }
    if (tid == 0) atomicMax((int*)&gm[1], __float_as_int(red[0]));
}

__global__ void pinv_init(const float* __restrict__ a, float* __restrict__ z,
                          const float* __restrict__ gm)
{
    long long t = (long long)blockIdx.x * 256 + threadIdx.x;
    int bh = (int)(t >> 16);
    int ij = (int)(t & 65535);
    int i = ij >> 8, j = ij & 255;
    float inv = 1.f / (gm[0] * gm[1]);
    z[((long long)bh << 16) + ij] = rtf(a[((long long)bh << 16) + (j << 8) + i] * inv);
}

// ---------------- depthwise conv, accumulates into 'of' layout ------------------
__global__ void conv_add_of(const float* __restrict__ v, const float* __restrict__ w,
                            float* __restrict__ of)
{
    long long t = (long long)blockIdx.x * 256 + threadIdx.x;
    int d = (int)(t & 63);
    long long r = t >> 6;
    int n  = (int)(r & 4095);
    int bh = (int)(r >> 12);
    int h  = bh & 7, b = bh >> 3;
    const float* vp = v + ((long long)bh << 18) + d;
    float s = 0.f;
#pragma unroll
    for (int tp = 0; tp < 33; tp++) {
        int nn = n + tp - 16;
        if (nn >= 0 && nn < 4096)
            s = fmaf(vp[(long long)nn << 6], w[h * 33 + tp], s);
    }
    long long oidx = ((long long)(b * 4096 + n)) * 512 + h * 64 + d;
    of[oidx] = rtf(of[oidx] + s);
}

// ---------------- host orchestration -------------------------------------------
extern "C" void kernel_launch(void* const* d_in, const int* in_sizes, int n_in,
                              void* d_out, int out_size)
{
    const float* x    = (const float*)d_in[0];
    const float* Wqkv = (const float*)d_in[1];
    const float* Wout = (const float*)d_in[2];
    const float* bout = (const float*)d_in[3];
    const float* rk   = (const float*)d_in[4];
    float* yout = (float*)d_out;

    float *xr, *wq, *wo, *q, *k, *v, *qlm, *klm, *s1, *a2, *s3, *z, *z2, *xz,
          *t1, *t3, *t5, *a3v, *zv, *of, *part, *gm;
    cudaGetSymbolAddress((void**)&xr,  g_x);
    cudaGetSymbolAddress((void**)&wq,  g_wq);
    cudaGetSymbolAddress((void**)&wo,  g_wo);
    cudaGetSymbolAddress((void**)&q,   g_q);
    cudaGetSymbolAddress((void**)&k,   g_k);
    cudaGetSymbolAddress((void**)&v,   g_v);
    cudaGetSymbolAddress((void**)&qlm, g_qlm);
    cudaGetSymbolAddress((void**)&klm, g_klm);
    cudaGetSymbolAddress((void**)&s1,  g_s1);
    cudaGetSymbolAddress((void**)&a2,  g_a2);
    cudaGetSymbolAddress((void**)&s3,  g_s3);
    cudaGetSymbolAddress((void**)&z,   g_z);
    cudaGetSymbolAddress((void**)&z2,  g_z2);
    cudaGetSymbolAddress((void**)&xz,  g_xz);
    cudaGetSymbolAddress((void**)&t1,  g_t1);
    cudaGetSymbolAddress((void**)&t3,  g_t3);
    cudaGetSymbolAddress((void**)&t5,  g_t5);
    cudaGetSymbolAddress((void**)&a3v, g_a3v);
    cudaGetSymbolAddress((void**)&zv,  g_zv);
    cudaGetSymbolAddress((void**)&of,  g_of);
    cudaGetSymbolAddress((void**)&part,g_part);
    cudaGetSymbolAddress((void**)&gm,  g_gmax);

    const long long sQ  = (long long)N_ * DH_;
    const long long sLM = (long long)M_ * DH_;
    const long long sS1 = (long long)N_ * M_;
    const long long sMM = (long long)M_ * M_;

    // dynamic smem sizes per instantiation
    const int smQKV = smem_bytes(128,128,0,5,4,32,3);
    const int smSM  = smem_bytes(64,256,1,7,8,16,4);
    const int smS3  = smem_bytes(128,128,1,0,4,16,4);
    const int smNS  = smem_bytes(128,128,0,0,4,32,3);
    const int sm64  = smem_bytes(128,64,0,0,2,32,3);
    const int smFP  = smem_bytes(128,128,0,4,4,32,3);

    static bool attr_done = false;
    if (!attr_done) {
        cudaFuncSetAttribute(gemm_tc<128,128,2,4,0,5,32,3>, cudaFuncAttributeMaxDynamicSharedMemorySize, smQKV);
        cudaFuncSetAttribute(gemm_tc<64,256,1,8,1,7,16,4>,  cudaFuncAttributeMaxDynamicSharedMemorySize, smSM);
        cudaFuncSetAttribute(gemm_tc<128,128,2,4,1,0,16,4,1,0>, cudaFuncAttributeMaxDynamicSharedMemorySize, smS3);
        cudaFuncSetAttribute(gemm_tc<128,128,2,4,0,3,32,3>, cudaFuncAttributeMaxDynamicSharedMemorySize, smNS);
        cudaFuncSetAttribute(gemm_tc<128,128,2,4,0,2,32,3>, cudaFuncAttributeMaxDynamicSharedMemorySize, smNS);
        cudaFuncSetAttribute(gemm_tc<128,128,2,4,0,0,32,3>, cudaFuncAttributeMaxDynamicSharedMemorySize, smNS);
        cudaFuncSetAttribute(gemm_tc<128,64,4,2,0,0,32,3,4,0>, cudaFuncAttributeMaxDynamicSharedMemorySize, sm64);
        cudaFuncSetAttribute(gemm_tc<128,64,4,2,0,0,32,3>, cudaFuncAttributeMaxDynamicSharedMemorySize, sm64);
        cudaFuncSetAttribute(gemm_tc<128,64,4,2,0,6,32,3>, cudaFuncAttributeMaxDynamicSharedMemorySize, sm64);
        cudaFuncSetAttribute(gemm_tc<128,128,2,4,0,4,32,3>, cudaFuncAttributeMaxDynamicSharedMemorySize, smFP);
        attr_done = true;
    }

    // 0. pre-round harness inputs to tf32
    round_copy<<<(B_*N_*DIM_) / 256, 256>>>(x, xr);
    round_copy<<<(DIM_*3*H_*DH_) / 256, 256>>>(Wqkv, wq);
    round_copy<<<(H_*DH_*DIM_) / 256, 256>>>(Wout, wo);

    // 1. qkv projection with scatter (K=512, BK32, 3-stage)
    gemm_tc<128,128,2,4,0,5,32,3><<<dim3(12, 128, 1), 256, smQKV>>>(
        512, xr, 512, 0, wq, 1536, 0,
        nullptr, 0, 0, 1.f, 0.f, nullptr, nullptr, q, k, v);

    // 2. landmarks
    landmarks_kernel<<<BH_ * M_, DH_>>>(q, k, qlm, klm);

    // 3. attn1 = softmax(q @ klm^T)   (K=64, BK16, 4-stage)
    gemm_tc<64,256,1,8,1,7,16,4><<<dim3(1, 64, BH_), 256, smSM>>>(
        64, q, 64, sQ, klm, 64, sLM,
        s1, 256, sS1, 1.f, 0.f, nullptr, nullptr, nullptr, nullptr, nullptr);

    // 4. attn2 = softmax(qlm @ klm^T)
    gemm_tc<64,256,1,8,1,7,16,4><<<dim3(1, 4, BH_), 256, smSM>>>(
        64, qlm, 64, sLM, klm, 64, sLM,
        a2, 256, sMM, 1.f, 0.f, nullptr, nullptr, nullptr, nullptr, nullptr);

    // 5. sim3 = qlm @ k^T (unrounded) ; softmax4096 rounds
    gemm_tc<128,128,2,4,1,0,16,4,1,0><<<dim3(32, 2, BH_), 256, smS3>>>(
        64, qlm, 64, sLM, k, 64, sQ,
        s3, 4096, (long long)M_ * N_, 1.f, 0.f, nullptr, nullptr, nullptr, nullptr, nullptr);
    softmax4096<<<BH_ * M_, 256>>>(s3);

    // 6. pinv init
    zero_gmax<<<1, 1>>>(gm);
    pinv_scales<<<BH_, 256>>>(a2, gm);
    pinv_init<<<(BH_ * M_ * M_) / 256, 256>>>(a2, z, gm);

    // 7. Newton-Schulz x6 (K=256, BK32, 3-stage)
    float* za = z;
    float* zb = z2;
    for (int it = 0; it < 6; it++) {
        gemm_tc<128,128,2,4,0,3,32,3><<<dim3(2, 2, BH_), 256, smNS>>>(
            256, a2, 256, sMM, za, 256, sMM,
            xz, 256, sMM, 1.f, 7.f, t1, nullptr, nullptr, nullptr, nullptr);
        gemm_tc<128,128,2,4,0,2,32,3><<<dim3(2, 2, BH_), 256, smNS>>>(
            256, xz, 256, sMM, t1, 256, sMM,
            t3, 256, sMM, 1.f, 15.f, nullptr, nullptr, nullptr, nullptr, nullptr);
        gemm_tc<128,128,2,4,0,2,32,3><<<dim3(2, 2, BH_), 256, smNS>>>(
            256, xz, 256, sMM, t3, 256, sMM,
            t5, 256, sMM, 1.f, 13.f, nullptr, nullptr, nullptr, nullptr, nullptr);
        gemm_tc<128,128,2,4,0,0,32,3><<<dim3(2, 2, BH_), 256, smNS>>>(
            256, za, 256, sMM, t5, 256, sMM,
            zb, 256, sMM, 0.25f, 0.f, nullptr, nullptr, nullptr, nullptr, nullptr);
        float* sw = za; za = zb; zb = sw;
    }

    // 8. a3v = attn3 @ v — split-K x4 (K slice 1024)
    gemm_tc<128,64,4,2,0,0,32,3,4,0><<<dim3(1, 2, BH_ * 4), 256, sm64>>>(
        1024, s3, 4096, (long long)M_ * N_, v, 64, sQ,
        part, 64, sLM, 1.f, 0.f, nullptr, nullptr, nullptr, nullptr, nullptr);
    reduce4<<<(BH_ * M_ * DH_) / 256, 256>>>(part, a3v);

    // 9. zv = z @ a3v
    gemm_tc<128,64,4,2,0,0,32,3><<<dim3(1, 2, BH_), 256, sm64>>>(
        256, za, 256, sMM, a3v, 64, sLM,
        zv, 64, sLM, 1.f, 0.f, nullptr, nullptr, nullptr, nullptr, nullptr);

    // 10. out = attn1 @ zv -> 'of'
    gemm_tc<128,64,4,2,0,6,32,3><<<dim3(1, 32, BH_), 256, sm64>>>(
        256, s1, 256, sS1, zv, 64, sLM,
        of, 0, 0, 1.f, 0.f, nullptr, nullptr, nullptr, nullptr, nullptr);

    // 11. += depthwise conv of v
    conv_add_of<<<(BH_ * N_ * DH_) / 256, 256>>>(v, rk, of);

    // 12. final projection
    gemm_tc<128,128,2,4,0,4,32,3><<<dim3(4, 128, 1), 256, smFP>>>(
        512, of, 512, 0, wo, 512, 0,
        yout, 512, 0, 1.f, 0.f, nullptr, bout, nullptr, nullptr, nullptr);
}